// round 10
// baseline (speedup 1.0000x reference)
#include <cuda_runtime.h>
#include <cuda_fp16.h>
#include <cstdint>

#define B_ 8192
#define M_ 256
#define N_ 512
#define NITER_ 16

// ---------------- device scratch (no allocation allowed) --------------------
__device__ __align__(128) __half g_yh[(size_t)B_ * M_], g_yl[(size_t)B_ * M_];
__device__ __align__(128) __half g_Wh[N_ * M_], g_Wl[N_ * M_];
__device__ __align__(128) __half g_Dh[N_ * N_], g_Dl[N_ * N_];
__device__ __align__(128) __half g_Sth[N_ * N_], g_Stl[N_ * N_];
__device__ __align__(128) __half g_Eh[N_ * N_], g_El[N_ * N_];
// Concatenated B for the fused iteration kernel: rows 0..511 = D^T, rows 512..1023 = F = E@D^T
__device__ __align__(128) __half g_Bch[2 * N_ * N_], g_Bcl[2 * N_ * N_];
__device__ __align__(128) __half g_Wyh[(size_t)B_ * N_], g_Wyl[(size_t)B_ * N_];
// Ping-pong P buffers
__device__ __align__(128) __half g_Pah[(size_t)B_ * N_], g_Pal[(size_t)B_ * N_];
__device__ __align__(128) __half g_Pbh[(size_t)B_ * N_], g_Pbl[(size_t)B_ * N_];
__device__ __align__(128) float g_Vf[(size_t)B_ * N_];

// ---------------- PTX helpers (compute_103 baseline ISA only) ---------------
__device__ __forceinline__ uint32_t smem_u32(const void* p) {
    uint32_t a;
    asm("{ .reg .u64 t; cvta.to.shared.u64 t, %1; cvt.u32.u64 %0, t; }"
        : "=r"(a) : "l"(p));
    return a;
}

__device__ __forceinline__ void cp16(uint32_t saddr, const void* gaddr) {
    asm volatile("cp.async.cg.shared.global [%0], [%1], 16;"
                 :: "r"(saddr), "l"(gaddr));
}
__device__ __forceinline__ void cp_commit() {
    asm volatile("cp.async.commit_group;");
}
template <int N>
__device__ __forceinline__ void cp_wait() {
    asm volatile("cp.async.wait_group %0;" :: "n"(N));
}

__device__ __forceinline__ uint4 ldsm_x4(uint32_t addr) {
    uint4 r;
    asm volatile("ldmatrix.sync.aligned.m8n8.x4.shared.b16 {%0,%1,%2,%3}, [%4];"
                 : "=r"(r.x), "=r"(r.y), "=r"(r.z), "=r"(r.w) : "r"(addr));
    return r;
}

// fp16 x fp16 -> fp32 accumulate (main term)
__device__ __forceinline__ void mma_f32acc(float* c, uint4 a, uint32_t b0, uint32_t b1) {
    asm volatile(
        "mma.sync.aligned.m16n8k16.row.col.f32.f16.f16.f32 "
        "{%0,%1,%2,%3}, {%4,%5,%6,%7}, {%8,%9}, {%0,%1,%2,%3};"
        : "+f"(c[0]), "+f"(c[1]), "+f"(c[2]), "+f"(c[3])
        : "r"(a.x), "r"(a.y), "r"(a.z), "r"(a.w), "r"(b0), "r"(b1));
}

// fp16 x fp16 -> fp16 accumulate (cross terms; 2x rate on fp32-acc-limited pipes)
__device__ __forceinline__ void mma_f16acc(uint2& c, uint4 a, uint32_t b0, uint32_t b1) {
    asm volatile(
        "mma.sync.aligned.m16n8k16.row.col.f16.f16.f16.f16 "
        "{%0,%1}, {%2,%3,%4,%5}, {%6,%7}, {%0,%1};"
        : "+r"(c.x), "+r"(c.y)
        : "r"(a.x), "r"(a.y), "r"(a.z), "r"(a.w), "r"(b0), "r"(b1));
}

__device__ __forceinline__ float soft_thr_f(float u, float t) {
    return fmaxf(u - t, 0.f) - fmaxf(-u - t, 0.f);
}

__device__ __forceinline__ void split_h(float a, __half& h, __half& l) {
    h = __float2half(a);
    l = __float2half(a - __half2float(h));
}

// ---------------- prologue / elementwise kernels ----------------------------
__global__ void split_mat(const float* __restrict__ in,
                          __half* __restrict__ hi,
                          __half* __restrict__ lo, int n) {
    int i = (blockIdx.x * blockDim.x + threadIdx.x) * 4;
    if (i >= n) return;
    float4 v = *(const float4*)(in + i);
    float x[4] = {v.x, v.y, v.z, v.w};
    __half h[4], l[4];
    #pragma unroll
    for (int j = 0; j < 4; j++) split_h(x[j], h[j], l[j]);
    *(__half2*)(hi + i)     = __halves2half2(h[0], h[1]);
    *(__half2*)(hi + i + 2) = __halves2half2(h[2], h[3]);
    *(__half2*)(lo + i)     = __halves2half2(l[0], l[1]);
    *(__half2*)(lo + i + 2) = __halves2half2(l[2], l[3]);
}

// P0 = soft_thr(V) split  (d0 = 0 makes the first step trivial)
__global__ void thr_split(const float* __restrict__ V,
                          __half* __restrict__ hi,
                          __half* __restrict__ lo,
                          const float* __restrict__ thr, int n) {
    int i = (blockIdx.x * blockDim.x + threadIdx.x) * 4;
    if (i >= n) return;
    float theta = __ldg(thr);
    float4 v = *(const float4*)(V + i);
    float x[4] = {v.x, v.y, v.z, v.w};
    __half h[4], l[4];
    #pragma unroll
    for (int j = 0; j < 4; j++) split_h(soft_thr_f(x[j], theta), h[j], l[j]);
    *(__half2*)(hi + i)     = __halves2half2(h[0], h[1]);
    *(__half2*)(hi + i + 2) = __halves2half2(h[2], h[3]);
    *(__half2*)(lo + i)     = __halves2half2(l[0], l[1]);
    *(__half2*)(lo + i + 2) = __halves2half2(l[2], l[3]);
}

// out = in^T for 512x512, emitting fp16 hi/lo split
__global__ void transpose_split512(const float* __restrict__ in,
                                   __half* __restrict__ hi,
                                   __half* __restrict__ lo) {
    __shared__ float tile[32][33];
    int x = blockIdx.x * 32 + threadIdx.x;
    int y0 = blockIdx.y * 32;
    #pragma unroll
    for (int j = threadIdx.y; j < 32; j += 8)
        tile[j][threadIdx.x] = in[(size_t)(y0 + j) * N_ + x];
    __syncthreads();
    int xo = blockIdx.y * 32 + threadIdx.x;
    int yo0 = blockIdx.x * 32;
    #pragma unroll
    for (int j = threadIdx.y; j < 32; j += 8) {
        float v = tile[threadIdx.x][j];
        __half h, l;
        split_h(v, h, l);
        size_t o = (size_t)(yo0 + j) * N_ + xo;
        hi[o] = h;
        lo[o] = l;
    }
}

// ---------------- shared split-fp16 mainloop (mma.sync) ---------------------
// 128x128 CTA tile of A @ Bm^T. 3-term: ah*bh (f32 acc) + al*bh + ah*bl (f16 acc).
// SMEM per stage 64KB (AH/AL/BH/BL 16KB each), 3 stages, K-chunk 64, 1 CTA/SM.
static constexpr int OFF_AH = 0;
static constexpr int OFF_AL = 16384;
static constexpr int OFF_BH = 32768;
static constexpr int OFF_BL = 49152;
static constexpr int STG = 65536;
static constexpr int SMEM_TOTAL = 3 * STG;  // 196608

__device__ __forceinline__ void issue_chunk(
    uint32_t stb, const __half* __restrict__ Ah, const __half* __restrict__ Al,
    const __half* __restrict__ Bh, const __half* __restrict__ Bl,
    int rowA0, int rowB0, int K, int kt, int tid) {
    #pragma unroll
    for (int i = 0; i < 4; i++) {
        int unit = tid + 256 * i;
        int row = unit >> 3, u = unit & 7;
        uint32_t so = (uint32_t)(row * 128 + ((u ^ (row & 7)) << 4));
        size_t goA = (size_t)(rowA0 + row) * K + kt * 64 + u * 8;
        size_t goB = (size_t)(rowB0 + row) * K + kt * 64 + u * 8;
        cp16(stb + OFF_AH + so, Ah + goA);
        cp16(stb + OFF_AL + so, Al + goA);
        cp16(stb + OFF_BH + so, Bh + goB);
        cp16(stb + OFF_BL + so, Bl + goB);
    }
    cp_commit();
}

__device__ __forceinline__ void mainloop_128x128(
    const __half* __restrict__ Ah, const __half* __restrict__ Al,
    const __half* __restrict__ Bh, const __half* __restrict__ Bl,
    int K, int rowA0, int rowB0, uint32_t sbase, int tid,
    float acc[4][4][4], uint2 acc16[4][4]) {
    const int lane = tid & 31;
    const int wid = tid >> 5;
    const int warp_m = wid & 1;
    const int warp_n = wid >> 1;

    const int rA = lane & 15;
    const int khA = lane >> 4;
    const int sxA = rA & 7;
    const int rB = ((lane >> 4) << 3) + (lane & 7);
    const int khB = (lane >> 3) & 1;
    const int sxB = rB & 7;

    uint32_t rowOffA[4], rowOffB[2];
    #pragma unroll
    for (int mi = 0; mi < 4; mi++)
        rowOffA[mi] = (warp_m * 64 + mi * 16 + rA) * 128;
    #pragma unroll
    for (int p = 0; p < 2; p++)
        rowOffB[p] = (warp_n * 32 + p * 16 + rB) * 128;

    const int KT = K >> 6;

    issue_chunk(sbase, Ah, Al, Bh, Bl, rowA0, rowB0, K, 0, tid);
    if (KT > 1) issue_chunk(sbase + STG, Ah, Al, Bh, Bl, rowA0, rowB0, K, 1, tid);

    int stage = 0;
    for (int kt = 0; kt < KT; kt++) {
        if (kt + 2 < KT) {
            int s2 = stage + 2; if (s2 >= 3) s2 -= 3;
            issue_chunk(sbase + s2 * STG, Ah, Al, Bh, Bl, rowA0, rowB0, K, kt + 2, tid);
            cp_wait<2>();
        } else if (kt + 2 == KT) {
            cp_wait<1>();
        } else {
            cp_wait<0>();
        }
        __syncthreads();

        const uint32_t st = sbase + stage * STG;
        #pragma unroll
        for (int ks = 0; ks < 4; ks++) {
            const uint32_t uA = (uint32_t)(((ks * 2 + khA) ^ sxA) << 4);
            const uint32_t uB = (uint32_t)(((ks * 2 + khB) ^ sxB) << 4);

            uint4 bh0 = ldsm_x4(st + OFF_BH + rowOffB[0] + uB);
            uint4 bh1 = ldsm_x4(st + OFF_BH + rowOffB[1] + uB);
            uint4 bl0 = ldsm_x4(st + OFF_BL + rowOffB[0] + uB);
            uint4 bl1 = ldsm_x4(st + OFF_BL + rowOffB[1] + uB);

            #pragma unroll
            for (int mi = 0; mi < 4; mi++) {
                uint4 ah = ldsm_x4(st + OFF_AH + rowOffA[mi] + uA);
                uint4 al = ldsm_x4(st + OFF_AL + rowOffA[mi] + uA);
                // main term: fp32 accumulate
                mma_f32acc(acc[mi][0], ah, bh0.x, bh0.y);
                mma_f32acc(acc[mi][1], ah, bh0.z, bh0.w);
                mma_f32acc(acc[mi][2], ah, bh1.x, bh1.y);
                mma_f32acc(acc[mi][3], ah, bh1.z, bh1.w);
                // cross terms: fp16 accumulate (tiny magnitude, double rate)
                mma_f16acc(acc16[mi][0], al, bh0.x, bh0.y);
                mma_f16acc(acc16[mi][0], ah, bl0.x, bl0.y);
                mma_f16acc(acc16[mi][1], al, bh0.z, bh0.w);
                mma_f16acc(acc16[mi][1], ah, bl0.z, bl0.w);
                mma_f16acc(acc16[mi][2], al, bh1.x, bh1.y);
                mma_f16acc(acc16[mi][2], ah, bl1.x, bl1.y);
                mma_f16acc(acc16[mi][3], al, bh1.z, bh1.w);
                mma_f16acc(acc16[mi][3], ah, bl1.z, bl1.w);
            }
        }
        __syncthreads();
        if (++stage == 3) stage = 0;
    }
}

// Merge f16 cross accumulators into the f32 accumulators.
__device__ __forceinline__ void merge_acc(float acc[4][4][4], uint2 acc16[4][4]) {
    #pragma unroll
    for (int mi = 0; mi < 4; mi++)
        #pragma unroll
        for (int ni = 0; ni < 4; ni++) {
            float2 lo = __half22float2(*(__half2*)&acc16[mi][ni].x);
            float2 hi = __half22float2(*(__half2*)&acc16[mi][ni].y);
            acc[mi][ni][0] += lo.x;
            acc[mi][ni][1] += lo.y;
            acc[mi][ni][2] += hi.x;
            acc[mi][ni][3] += hi.y;
        }
}

#define INIT_ACC()                                                             \
    float acc[4][4][4];                                                        \
    uint2 acc16[4][4];                                                         \
    _Pragma("unroll")                                                          \
    for (int a = 0; a < 4; a++) {                                              \
        _Pragma("unroll")                                                      \
        for (int b = 0; b < 4; b++) {                                          \
            acc16[a][b].x = 0u; acc16[a][b].y = 0u;                            \
            _Pragma("unroll")                                                  \
            for (int c = 0; c < 4; c++) acc[a][b][c] = 0.f;                    \
        }                                                                      \
    }

// ---------------- generic GEMM (prologue) -----------------------------------
template <bool WF32, bool WSPLIT>
__global__ __launch_bounds__(256, 1)
void gemm_tc(const __half* __restrict__ Ah, const __half* __restrict__ Al,
             const __half* __restrict__ Bh, const __half* __restrict__ Bl,
             float* __restrict__ Cf,
             __half* __restrict__ Chi, __half* __restrict__ Clo,
             int K) {
    extern __shared__ char sm[];
    const uint32_t sbase = smem_u32(sm);
    const int tid = threadIdx.x;
    const int lane = tid & 31;
    const int wid = tid >> 5;
    const int warp_m = wid & 1;
    const int warp_n = wid >> 1;

    INIT_ACC();
    mainloop_128x128(Ah, Al, Bh, Bl, K, blockIdx.y * 128, blockIdx.x * 128,
                     sbase, tid, acc, acc16);
    merge_acc(acc, acc16);

    const int g = lane >> 2, tm = lane & 3;
    #pragma unroll
    for (int mi = 0; mi < 4; mi++) {
        #pragma unroll
        for (int half = 0; half < 2; half++) {
            const int row = blockIdx.y * 128 + warp_m * 64 + mi * 16 + g + half * 8;
            #pragma unroll
            for (int ni = 0; ni < 4; ni++) {
                const int col = blockIdx.x * 128 + warp_n * 32 + ni * 8 + tm * 2;
                size_t off = (size_t)row * N_ + col;
                float c0 = acc[mi][ni][half * 2 + 0];
                float c1 = acc[mi][ni][half * 2 + 1];
                if (WF32) *(float2*)(Cf + off) = make_float2(c0, c1);
                if (WSPLIT) {
                    __half h0, l0, h1, l1;
                    split_h(c0, h0, l0);
                    split_h(c1, h1, l1);
                    *(__half2*)(Chi + off) = __halves2half2(h0, h1);
                    *(__half2*)(Clo + off) = __halves2half2(l0, l1);
                }
            }
        }
    }
}

// ---------------- fused iteration GEMM --------------------------------------
// Grid (8, 64): bx 0..3 -> d_{t+1} = P @ Dt^T (fp32 to out slot)
//               bx 4..7 -> P_{t+1} = soft_thr(P @ F^T + V) (split to Pn)
// B operand = concatenated [Dt | F] (1024 x 512).
__global__ __launch_bounds__(256, 1)
void gemm_fused(const __half* __restrict__ Ph, const __half* __restrict__ Pl,
                const __half* __restrict__ Bch, const __half* __restrict__ Bcl,
                const float* __restrict__ Vf, float* __restrict__ outSlot,
                __half* __restrict__ Pnh, __half* __restrict__ Pnl,
                const float* __restrict__ thr) {
    extern __shared__ char sm[];
    const uint32_t sbase = smem_u32(sm);
    const int tid = threadIdx.x;
    const int lane = tid & 31;
    const int wid = tid >> 5;
    const int warp_m = wid & 1;
    const int warp_n = wid >> 1;
    const int bx = blockIdx.x, by = blockIdx.y;

    INIT_ACC();
    mainloop_128x128(Ph, Pl, Bch, Bcl, N_, by * 128, bx * 128, sbase, tid,
                     acc, acc16);
    merge_acc(acc, acc16);

    const bool isP = bx >= 4;
    const int colbase = (bx & 3) * 128;
    const float theta = __ldg(thr);
    const int g = lane >> 2, tm = lane & 3;

    #pragma unroll
    for (int mi = 0; mi < 4; mi++) {
        #pragma unroll
        for (int half = 0; half < 2; half++) {
            const int row = by * 128 + warp_m * 64 + mi * 16 + g + half * 8;
            #pragma unroll
            for (int ni = 0; ni < 4; ni++) {
                const int col = colbase + warp_n * 32 + ni * 8 + tm * 2;
                size_t off = (size_t)row * N_ + col;
                float c0 = acc[mi][ni][half * 2 + 0];
                float c1 = acc[mi][ni][half * 2 + 1];
                if (!isP) {
                    *(float2*)(outSlot + off) = make_float2(c0, c1);
                } else {
                    float2 v = *(const float2*)(Vf + off);
                    c0 = soft_thr_f(c0 + v.x, theta);
                    c1 = soft_thr_f(c1 + v.y, theta);
                    __half h0, l0, h1, l1;
                    split_h(c0, h0, l0);
                    split_h(c1, h1, l1);
                    *(__half2*)(Pnh + off) = __halves2half2(h0, h1);
                    *(__half2*)(Pnl + off) = __halves2half2(l0, l1);
                }
            }
        }
    }
}

// ---------------- launch ----------------------------------------------------
extern "C" void kernel_launch(void* const* d_in, const int* in_sizes, int n_in,
                              void* d_out, int out_size) {
    const float* y   = (const float*)d_in[0];  // (B, M)
    const float* S   = (const float*)d_in[1];  // (N, N)
    const float* W   = (const float*)d_in[2];  // (N, M)
    const float* D   = (const float*)d_in[3];  // (N, N)
    const float* thr = (const float*)d_in[4];  // (1, 1)
    float* out = (float*)d_out;                // (NITER+1, B, N)

    __half *yh, *yl, *Wh, *Wl, *Dh, *Dl, *Sth, *Stl, *Eh, *El;
    __half *Bch, *Bcl, *Wyh, *Wyl, *Pah, *Pal, *Pbh, *Pbl;
    float* Vf;
    cudaGetSymbolAddress((void**)&yh, g_yh);   cudaGetSymbolAddress((void**)&yl, g_yl);
    cudaGetSymbolAddress((void**)&Wh, g_Wh);   cudaGetSymbolAddress((void**)&Wl, g_Wl);
    cudaGetSymbolAddress((void**)&Dh, g_Dh);   cudaGetSymbolAddress((void**)&Dl, g_Dl);
    cudaGetSymbolAddress((void**)&Sth, g_Sth); cudaGetSymbolAddress((void**)&Stl, g_Stl);
    cudaGetSymbolAddress((void**)&Eh, g_Eh);   cudaGetSymbolAddress((void**)&El, g_El);
    cudaGetSymbolAddress((void**)&Bch, g_Bch); cudaGetSymbolAddress((void**)&Bcl, g_Bcl);
    cudaGetSymbolAddress((void**)&Wyh, g_Wyh); cudaGetSymbolAddress((void**)&Wyl, g_Wyl);
    cudaGetSymbolAddress((void**)&Pah, g_Pah); cudaGetSymbolAddress((void**)&Pal, g_Pal);
    cudaGetSymbolAddress((void**)&Pbh, g_Pbh); cudaGetSymbolAddress((void**)&Pbl, g_Pbl);
    cudaGetSymbolAddress((void**)&Vf, g_Vf);

    cudaFuncSetAttribute((const void*)gemm_tc<false, true>,
                         cudaFuncAttributeMaxDynamicSharedMemorySize, SMEM_TOTAL);
    cudaFuncSetAttribute((const void*)gemm_tc<true, false>,
                         cudaFuncAttributeMaxDynamicSharedMemorySize, SMEM_TOTAL);
    cudaFuncSetAttribute((const void*)gemm_fused,
                         cudaFuncAttributeMaxDynamicSharedMemorySize, SMEM_TOTAL);

    const size_t BN = (size_t)B_ * N_;
    dim3 tb(32, 8), tg(16, 16);
    dim3 gBig(N_ / 128, B_ / 128);   // (4, 64)
    dim3 gSmall(N_ / 128, N_ / 128); // (4, 4)
    dim3 gFull(8, B_ / 128);         // (8, 64)

    // ---- prologue ----
    split_mat<<<(B_ * M_ / 4 + 255) / 256, 256>>>(y, yh, yl, B_ * M_);
    split_mat<<<(N_ * M_ / 4 + 255) / 256, 256>>>(W, Wh, Wl, N_ * M_);
    split_mat<<<(N_ * N_ / 4 + 255) / 256, 256>>>(D, Dh, Dl, N_ * N_);
    transpose_split512<<<tg, tb>>>(S, Sth, Stl);          // S^T split
    transpose_split512<<<tg, tb>>>(D, Bch, Bcl);          // D^T -> Bcat rows 0..511

    // Wy = y @ W^T (K=256) -> split
    gemm_tc<false, true><<<gBig, 256, SMEM_TOTAL>>>(
        yh, yl, Wh, Wl, nullptr, Wyh, Wyl, M_);
    // E = D @ S = D @ St^T -> split
    gemm_tc<false, true><<<gSmall, 256, SMEM_TOTAL>>>(
        Dh, Dl, Sth, Stl, nullptr, Eh, El, N_);
    // V = Wy @ D^T -> fp32
    gemm_tc<true, false><<<gBig, 256, SMEM_TOTAL>>>(
        Wyh, Wyl, Dh, Dl, Vf, nullptr, nullptr, N_);
    // F = E @ D^T -> split into Bcat rows 512..1023
    gemm_tc<false, true><<<gSmall, 256, SMEM_TOTAL>>>(
        Eh, El, Dh, Dl, nullptr, Bch + (size_t)N_ * N_, Bcl + (size_t)N_ * N_, N_);

    // d0 = 0 slot; P0 = soft_thr(V)
    cudaMemsetAsync(out, 0, BN * sizeof(float));
    thr_split<<<((int)BN / 4 + 255) / 256, 256>>>(Vf, Pah, Pal, thr, (int)BN);

    // Iterations: launch t reads P_t, writes out[t+1] (=P_t@Dt^T) and
    // P_{t+1} = soft_thr(P_t@F^T + V). Last launch: d-half only (grid 4x64).
    for (int t = 0; t < NITER_; t++) {
        float* d_next = out + (size_t)(t + 1) * BN;
        const __half* Ah = (t & 1) ? Pbh : Pah;
        const __half* Al = (t & 1) ? Pbl : Pal;
        __half* Pnh = (t & 1) ? Pah : Pbh;
        __half* Pnl = (t & 1) ? Pal : Pbl;
        if (t + 1 < NITER_) {
            gemm_fused<<<gFull, 256, SMEM_TOTAL>>>(
                Ah, Al, Bch, Bcl, Vf, d_next, Pnh, Pnl, thr);
        } else {
            gemm_fused<<<gBig, 256, SMEM_TOTAL>>>(
                Ah, Al, Bch, Bcl, Vf, d_next, Pnh, Pnl, thr);
        }
    }
}

// round 12
// speedup vs baseline: 1.7385x; 1.7385x over previous
#include <cuda_runtime.h>
#include <cuda_fp16.h>
#include <cstdint>

#define B_ 8192
#define M_ 256
#define N_ 512
#define NITER_ 16

// ---------------- device scratch (no allocation allowed) --------------------
__device__ __align__(128) __half g_yh[(size_t)B_ * M_], g_yl[(size_t)B_ * M_];
__device__ __align__(128) __half g_Wh[N_ * M_], g_Wl[N_ * M_];
__device__ __align__(128) __half g_Dh[N_ * N_], g_Dl[N_ * N_];
__device__ __align__(128) __half g_Sth[N_ * N_], g_Stl[N_ * N_];
__device__ __align__(128) __half g_Eh[N_ * N_], g_El[N_ * N_];
// Concatenated B for the fused iteration kernel: rows 0..511 = D^T, rows 512..1023 = F = E@D^T
__device__ __align__(128) __half g_Bch[2 * N_ * N_], g_Bcl[2 * N_ * N_];
__device__ __align__(128) __half g_Wyh[(size_t)B_ * N_], g_Wyl[(size_t)B_ * N_];
// Ping-pong P buffers
__device__ __align__(128) __half g_Pah[(size_t)B_ * N_], g_Pal[(size_t)B_ * N_];
__device__ __align__(128) __half g_Pbh[(size_t)B_ * N_], g_Pbl[(size_t)B_ * N_];
__device__ __align__(128) float g_Vf[(size_t)B_ * N_];

// ---------------- PTX helpers (compute_103 baseline ISA only) ---------------
__device__ __forceinline__ uint32_t smem_u32(const void* p) {
    uint32_t a;
    asm("{ .reg .u64 t; cvta.to.shared.u64 t, %1; cvt.u32.u64 %0, t; }"
        : "=r"(a) : "l"(p));
    return a;
}

__device__ __forceinline__ void cp16(uint32_t saddr, const void* gaddr) {
    asm volatile("cp.async.cg.shared.global [%0], [%1], 16;"
                 :: "r"(saddr), "l"(gaddr));
}
__device__ __forceinline__ void cp_commit() {
    asm volatile("cp.async.commit_group;");
}
template <int N>
__device__ __forceinline__ void cp_wait() {
    asm volatile("cp.async.wait_group %0;" :: "n"(N));
}

__device__ __forceinline__ uint4 ldsm_x4(uint32_t addr) {
    uint4 r;
    asm volatile("ldmatrix.sync.aligned.m8n8.x4.shared.b16 {%0,%1,%2,%3}, [%4];"
                 : "=r"(r.x), "=r"(r.y), "=r"(r.z), "=r"(r.w) : "r"(addr));
    return r;
}

// fp16 x fp16 -> fp32 accumulate
__device__ __forceinline__ void mma16(float* c, uint4 a, uint32_t b0, uint32_t b1) {
    asm volatile(
        "mma.sync.aligned.m16n8k16.row.col.f32.f16.f16.f32 "
        "{%0,%1,%2,%3}, {%4,%5,%6,%7}, {%8,%9}, {%0,%1,%2,%3};"
        : "+f"(c[0]), "+f"(c[1]), "+f"(c[2]), "+f"(c[3])
        : "r"(a.x), "r"(a.y), "r"(a.z), "r"(a.w), "r"(b0), "r"(b1));
}

__device__ __forceinline__ float soft_thr_f(float u, float t) {
    return fmaxf(u - t, 0.f) - fmaxf(-u - t, 0.f);
}

__device__ __forceinline__ void split_h(float a, __half& h, __half& l) {
    h = __float2half(a);
    l = __float2half(a - __half2float(h));
}

// ---------------- prologue / elementwise kernels ----------------------------
__global__ void split_mat(const float* __restrict__ in,
                          __half* __restrict__ hi,
                          __half* __restrict__ lo, int n) {
    int i = (blockIdx.x * blockDim.x + threadIdx.x) * 4;
    if (i >= n) return;
    float4 v = *(const float4*)(in + i);
    float x[4] = {v.x, v.y, v.z, v.w};
    __half h[4], l[4];
    #pragma unroll
    for (int j = 0; j < 4; j++) split_h(x[j], h[j], l[j]);
    *(__half2*)(hi + i)     = __halves2half2(h[0], h[1]);
    *(__half2*)(hi + i + 2) = __halves2half2(h[2], h[3]);
    *(__half2*)(lo + i)     = __halves2half2(l[0], l[1]);
    *(__half2*)(lo + i + 2) = __halves2half2(l[2], l[3]);
}

// P0 = soft_thr(V) split  (d0 = 0 makes the first step trivial)
__global__ void thr_split(const float* __restrict__ V,
                          __half* __restrict__ hi,
                          __half* __restrict__ lo,
                          const float* __restrict__ thr, int n) {
    int i = (blockIdx.x * blockDim.x + threadIdx.x) * 4;
    if (i >= n) return;
    float theta = __ldg(thr);
    float4 v = *(const float4*)(V + i);
    float x[4] = {v.x, v.y, v.z, v.w};
    __half h[4], l[4];
    #pragma unroll
    for (int j = 0; j < 4; j++) split_h(soft_thr_f(x[j], theta), h[j], l[j]);
    *(__half2*)(hi + i)     = __halves2half2(h[0], h[1]);
    *(__half2*)(hi + i + 2) = __halves2half2(h[2], h[3]);
    *(__half2*)(lo + i)     = __halves2half2(l[0], l[1]);
    *(__half2*)(lo + i + 2) = __halves2half2(l[2], l[3]);
}

// out = in^T for 512x512, emitting fp16 hi/lo split
__global__ void transpose_split512(const float* __restrict__ in,
                                   __half* __restrict__ hi,
                                   __half* __restrict__ lo) {
    __shared__ float tile[32][33];
    int x = blockIdx.x * 32 + threadIdx.x;
    int y0 = blockIdx.y * 32;
    #pragma unroll
    for (int j = threadIdx.y; j < 32; j += 8)
        tile[j][threadIdx.x] = in[(size_t)(y0 + j) * N_ + x];
    __syncthreads();
    int xo = blockIdx.y * 32 + threadIdx.x;
    int yo0 = blockIdx.x * 32;
    #pragma unroll
    for (int j = threadIdx.y; j < 32; j += 8) {
        float v = tile[threadIdx.x][j];
        __half h, l;
        split_h(v, h, l);
        size_t o = (size_t)(yo0 + j) * N_ + xo;
        hi[o] = h;
        lo[o] = l;
    }
}

// ---------------- shared split-fp16 mainloop (mma.sync) ---------------------
// 128x128 CTA tile of A @ Bm^T.
// TERMS==3: ah*bh + al*bh + ah*bl (all f32 acc) — recurrence-grade precision.
// TERMS==2: ah*bh + al*bh (skips BL loads entirely) — output-grade precision.
// SMEM per stage 64KB (AH/AL/BH/BL 16KB each), 3 stages, K-chunk 64, 1 CTA/SM.
static constexpr int OFF_AH = 0;
static constexpr int OFF_AL = 16384;
static constexpr int OFF_BH = 32768;
static constexpr int OFF_BL = 49152;
static constexpr int STG = 65536;
static constexpr int SMEM_TOTAL = 3 * STG;  // 196608

template <int TERMS>
__device__ __forceinline__ void issue_chunk(
    uint32_t stb, const __half* __restrict__ Ah, const __half* __restrict__ Al,
    const __half* __restrict__ Bh, const __half* __restrict__ Bl,
    int rowA0, int rowB0, int K, int kt, int tid) {
    #pragma unroll
    for (int i = 0; i < 4; i++) {
        int unit = tid + 256 * i;
        int row = unit >> 3, u = unit & 7;
        uint32_t so = (uint32_t)(row * 128 + ((u ^ (row & 7)) << 4));
        size_t goA = (size_t)(rowA0 + row) * K + kt * 64 + u * 8;
        size_t goB = (size_t)(rowB0 + row) * K + kt * 64 + u * 8;
        cp16(stb + OFF_AH + so, Ah + goA);
        cp16(stb + OFF_AL + so, Al + goA);
        cp16(stb + OFF_BH + so, Bh + goB);
        if (TERMS == 3) cp16(stb + OFF_BL + so, Bl + goB);
    }
    cp_commit();
}

template <int TERMS>
__device__ __forceinline__ void mainloop_128x128(
    const __half* __restrict__ Ah, const __half* __restrict__ Al,
    const __half* __restrict__ Bh, const __half* __restrict__ Bl,
    int K, int rowA0, int rowB0, uint32_t sbase, int tid,
    float acc[4][4][4]) {
    const int lane = tid & 31;
    const int wid = tid >> 5;
    const int warp_m = wid & 1;
    const int warp_n = wid >> 1;

    const int rA = lane & 15;
    const int khA = lane >> 4;
    const int sxA = rA & 7;
    const int rB = ((lane >> 4) << 3) + (lane & 7);
    const int khB = (lane >> 3) & 1;
    const int sxB = rB & 7;

    uint32_t rowOffA[4], rowOffB[2];
    #pragma unroll
    for (int mi = 0; mi < 4; mi++)
        rowOffA[mi] = (warp_m * 64 + mi * 16 + rA) * 128;
    #pragma unroll
    for (int p = 0; p < 2; p++)
        rowOffB[p] = (warp_n * 32 + p * 16 + rB) * 128;

    const int KT = K >> 6;

    issue_chunk<TERMS>(sbase, Ah, Al, Bh, Bl, rowA0, rowB0, K, 0, tid);
    if (KT > 1) issue_chunk<TERMS>(sbase + STG, Ah, Al, Bh, Bl, rowA0, rowB0, K, 1, tid);

    int stage = 0;
    for (int kt = 0; kt < KT; kt++) {
        if (kt + 2 < KT) {
            int s2 = stage + 2; if (s2 >= 3) s2 -= 3;
            issue_chunk<TERMS>(sbase + s2 * STG, Ah, Al, Bh, Bl, rowA0, rowB0, K, kt + 2, tid);
            cp_wait<2>();
        } else if (kt + 2 == KT) {
            cp_wait<1>();
        } else {
            cp_wait<0>();
        }
        __syncthreads();

        const uint32_t st = sbase + stage * STG;
        #pragma unroll
        for (int ks = 0; ks < 4; ks++) {
            const uint32_t uA = (uint32_t)(((ks * 2 + khA) ^ sxA) << 4);
            const uint32_t uB = (uint32_t)(((ks * 2 + khB) ^ sxB) << 4);

            uint4 bh0 = ldsm_x4(st + OFF_BH + rowOffB[0] + uB);
            uint4 bh1 = ldsm_x4(st + OFF_BH + rowOffB[1] + uB);
            uint4 bl0, bl1;
            if (TERMS == 3) {
                bl0 = ldsm_x4(st + OFF_BL + rowOffB[0] + uB);
                bl1 = ldsm_x4(st + OFF_BL + rowOffB[1] + uB);
            }

            #pragma unroll
            for (int mi = 0; mi < 4; mi++) {
                uint4 ah = ldsm_x4(st + OFF_AH + rowOffA[mi] + uA);
                uint4 al = ldsm_x4(st + OFF_AL + rowOffA[mi] + uA);
                mma16(acc[mi][0], ah, bh0.x, bh0.y);
                mma16(acc[mi][0], al, bh0.x, bh0.y);
                mma16(acc[mi][1], ah, bh0.z, bh0.w);
                mma16(acc[mi][1], al, bh0.z, bh0.w);
                mma16(acc[mi][2], ah, bh1.x, bh1.y);
                mma16(acc[mi][2], al, bh1.x, bh1.y);
                mma16(acc[mi][3], ah, bh1.z, bh1.w);
                mma16(acc[mi][3], al, bh1.z, bh1.w);
                if (TERMS == 3) {
                    mma16(acc[mi][0], ah, bl0.x, bl0.y);
                    mma16(acc[mi][1], ah, bl0.z, bl0.w);
                    mma16(acc[mi][2], ah, bl1.x, bl1.y);
                    mma16(acc[mi][3], ah, bl1.z, bl1.w);
                }
            }
        }
        __syncthreads();
        if (++stage == 3) stage = 0;
    }
}

#define INIT_ACC()                                                             \
    float acc[4][4][4];                                                        \
    _Pragma("unroll")                                                          \
    for (int a = 0; a < 4; a++)                                                \
        _Pragma("unroll")                                                      \
        for (int b = 0; b < 4; b++)                                            \
            _Pragma("unroll")                                                  \
            for (int c = 0; c < 4; c++) acc[a][b][c] = 0.f;

// ---------------- generic GEMM (prologue, 3-term) ---------------------------
template <bool WF32, bool WSPLIT>
__global__ __launch_bounds__(256, 1)
void gemm_tc(const __half* __restrict__ Ah, const __half* __restrict__ Al,
             const __half* __restrict__ Bh, const __half* __restrict__ Bl,
             float* __restrict__ Cf,
             __half* __restrict__ Chi, __half* __restrict__ Clo,
             int K) {
    extern __shared__ char sm[];
    const uint32_t sbase = smem_u32(sm);
    const int tid = threadIdx.x;
    const int lane = tid & 31;
    const int wid = tid >> 5;
    const int warp_m = wid & 1;
    const int warp_n = wid >> 1;

    INIT_ACC();
    mainloop_128x128<3>(Ah, Al, Bh, Bl, K, blockIdx.y * 128, blockIdx.x * 128,
                        sbase, tid, acc);

    const int g = lane >> 2, tm = lane & 3;
    #pragma unroll
    for (int mi = 0; mi < 4; mi++) {
        #pragma unroll
        for (int half = 0; half < 2; half++) {
            const int row = blockIdx.y * 128 + warp_m * 64 + mi * 16 + g + half * 8;
            #pragma unroll
            for (int ni = 0; ni < 4; ni++) {
                const int col = blockIdx.x * 128 + warp_n * 32 + ni * 8 + tm * 2;
                size_t off = (size_t)row * N_ + col;
                float c0 = acc[mi][ni][half * 2 + 0];
                float c1 = acc[mi][ni][half * 2 + 1];
                if (WF32) *(float2*)(Cf + off) = make_float2(c0, c1);
                if (WSPLIT) {
                    __half h0, l0, h1, l1;
                    split_h(c0, h0, l0);
                    split_h(c1, h1, l1);
                    *(__half2*)(Chi + off) = __halves2half2(h0, h1);
                    *(__half2*)(Clo + off) = __halves2half2(l0, l1);
                }
            }
        }
    }
}

// ---------------- fused iteration GEMM --------------------------------------
// Grid (8, 64): bx 0..3 -> d_{t+1} = P @ Dt^T (fp32 to out slot) [2-term]
//               bx 4..7 -> P_{t+1} = soft_thr(P @ F^T + V) (split) [3-term]
// B operand = concatenated [Dt | F] (1024 x 512).
__global__ __launch_bounds__(256, 1)
void gemm_fused(const __half* __restrict__ Ph, const __half* __restrict__ Pl,
                const __half* __restrict__ Bch, const __half* __restrict__ Bcl,
                const float* __restrict__ Vf, float* __restrict__ outSlot,
                __half* __restrict__ Pnh, __half* __restrict__ Pnl,
                const float* __restrict__ thr) {
    extern __shared__ char sm[];
    const uint32_t sbase = smem_u32(sm);
    const int tid = threadIdx.x;
    const int lane = tid & 31;
    const int wid = tid >> 5;
    const int warp_m = wid & 1;
    const int warp_n = wid >> 1;
    const int bx = blockIdx.x, by = blockIdx.y;
    const bool isP = bx >= 4;

    INIT_ACC();
    if (isP) {
        mainloop_128x128<3>(Ph, Pl, Bch, Bcl, N_, by * 128, bx * 128, sbase, tid, acc);
    } else {
        mainloop_128x128<2>(Ph, Pl, Bch, Bcl, N_, by * 128, bx * 128, sbase, tid, acc);
    }

    const int colbase = (bx & 3) * 128;
    const float theta = __ldg(thr);
    const int g = lane >> 2, tm = lane & 3;

    #pragma unroll
    for (int mi = 0; mi < 4; mi++) {
        #pragma unroll
        for (int half = 0; half < 2; half++) {
            const int row = by * 128 + warp_m * 64 + mi * 16 + g + half * 8;
            #pragma unroll
            for (int ni = 0; ni < 4; ni++) {
                const int col = colbase + warp_n * 32 + ni * 8 + tm * 2;
                size_t off = (size_t)row * N_ + col;
                float c0 = acc[mi][ni][half * 2 + 0];
                float c1 = acc[mi][ni][half * 2 + 1];
                if (!isP) {
                    *(float2*)(outSlot + off) = make_float2(c0, c1);
                } else {
                    float2 v = *(const float2*)(Vf + off);
                    c0 = soft_thr_f(c0 + v.x, theta);
                    c1 = soft_thr_f(c1 + v.y, theta);
                    __half h0, l0, h1, l1;
                    split_h(c0, h0, l0);
                    split_h(c1, h1, l1);
                    *(__half2*)(Pnh + off) = __halves2half2(h0, h1);
                    *(__half2*)(Pnl + off) = __halves2half2(l0, l1);
                }
            }
        }
    }
}

// ---------------- launch ----------------------------------------------------
extern "C" void kernel_launch(void* const* d_in, const int* in_sizes, int n_in,
                              void* d_out, int out_size) {
    const float* y   = (const float*)d_in[0];  // (B, M)
    const float* S   = (const float*)d_in[1];  // (N, N)
    const float* W   = (const float*)d_in[2];  // (N, M)
    const float* D   = (const float*)d_in[3];  // (N, N)
    const float* thr = (const float*)d_in[4];  // (1, 1)
    float* out = (float*)d_out;                // (NITER+1, B, N)

    __half *yh, *yl, *Wh, *Wl, *Dh, *Dl, *Sth, *Stl, *Eh, *El;
    __half *Bch, *Bcl, *Wyh, *Wyl, *Pah, *Pal, *Pbh, *Pbl;
    float* Vf;
    cudaGetSymbolAddress((void**)&yh, g_yh);   cudaGetSymbolAddress((void**)&yl, g_yl);
    cudaGetSymbolAddress((void**)&Wh, g_Wh);   cudaGetSymbolAddress((void**)&Wl, g_Wl);
    cudaGetSymbolAddress((void**)&Dh, g_Dh);   cudaGetSymbolAddress((void**)&Dl, g_Dl);
    cudaGetSymbolAddress((void**)&Sth, g_Sth); cudaGetSymbolAddress((void**)&Stl, g_Stl);
    cudaGetSymbolAddress((void**)&Eh, g_Eh);   cudaGetSymbolAddress((void**)&El, g_El);
    cudaGetSymbolAddress((void**)&Bch, g_Bch); cudaGetSymbolAddress((void**)&Bcl, g_Bcl);
    cudaGetSymbolAddress((void**)&Wyh, g_Wyh); cudaGetSymbolAddress((void**)&Wyl, g_Wyl);
    cudaGetSymbolAddress((void**)&Pah, g_Pah); cudaGetSymbolAddress((void**)&Pal, g_Pal);
    cudaGetSymbolAddress((void**)&Pbh, g_Pbh); cudaGetSymbolAddress((void**)&Pbl, g_Pbl);
    cudaGetSymbolAddress((void**)&Vf, g_Vf);

    cudaFuncSetAttribute((const void*)gemm_tc<false, true>,
                         cudaFuncAttributeMaxDynamicSharedMemorySize, SMEM_TOTAL);
    cudaFuncSetAttribute((const void*)gemm_tc<true, false>,
                         cudaFuncAttributeMaxDynamicSharedMemorySize, SMEM_TOTAL);
    cudaFuncSetAttribute((const void*)gemm_fused,
                         cudaFuncAttributeMaxDynamicSharedMemorySize, SMEM_TOTAL);

    const size_t BN = (size_t)B_ * N_;
    dim3 tb(32, 8), tg(16, 16);
    dim3 gBig(N_ / 128, B_ / 128);   // (4, 64)
    dim3 gSmall(N_ / 128, N_ / 128); // (4, 4)
    dim3 gFull(8, B_ / 128);         // (8, 64)

    // ---- prologue ----
    split_mat<<<(B_ * M_ / 4 + 255) / 256, 256>>>(y, yh, yl, B_ * M_);
    split_mat<<<(N_ * M_ / 4 + 255) / 256, 256>>>(W, Wh, Wl, N_ * M_);
    split_mat<<<(N_ * N_ / 4 + 255) / 256, 256>>>(D, Dh, Dl, N_ * N_);
    transpose_split512<<<tg, tb>>>(S, Sth, Stl);          // S^T split
    transpose_split512<<<tg, tb>>>(D, Bch, Bcl);          // D^T -> Bcat rows 0..511

    // Wy = y @ W^T (K=256) -> split
    gemm_tc<false, true><<<gBig, 256, SMEM_TOTAL>>>(
        yh, yl, Wh, Wl, nullptr, Wyh, Wyl, M_);
    // E = D @ S = D @ St^T -> split
    gemm_tc<false, true><<<gSmall, 256, SMEM_TOTAL>>>(
        Dh, Dl, Sth, Stl, nullptr, Eh, El, N_);
    // V = Wy @ D^T -> fp32
    gemm_tc<true, false><<<gBig, 256, SMEM_TOTAL>>>(
        Wyh, Wyl, Dh, Dl, Vf, nullptr, nullptr, N_);
    // F = E @ D^T -> split into Bcat rows 512..1023
    gemm_tc<false, true><<<gSmall, 256, SMEM_TOTAL>>>(
        Eh, El, Dh, Dl, nullptr, Bch + (size_t)N_ * N_, Bcl + (size_t)N_ * N_, N_);

    // d0 = 0 slot; P0 = soft_thr(V)
    cudaMemsetAsync(out, 0, BN * sizeof(float));
    thr_split<<<((int)BN / 4 + 255) / 256, 256>>>(Vf, Pah, Pal, thr, (int)BN);

    // Iterations: launch t reads P_t, writes out[t+1] (=P_t@Dt^T, 2-term) and
    // P_{t+1} = soft_thr(P_t@F^T + V) (3-term). Last launch: d-half only.
    for (int t = 0; t < NITER_; t++) {
        float* d_next = out + (size_t)(t + 1) * BN;
        const __half* Ah = (t & 1) ? Pbh : Pah;
        const __half* Al = (t & 1) ? Pbl : Pal;
        __half* Pnh = (t & 1) ? Pah : Pbh;
        __half* Pnl = (t & 1) ? Pal : Pbl;
        if (t + 1 < NITER_) {
            gemm_fused<<<gFull, 256, SMEM_TOTAL>>>(
                Ah, Al, Bch, Bcl, Vf, d_next, Pnh, Pnl, thr);
        } else {
            gemm_fused<<<gBig, 256, SMEM_TOTAL>>>(
                Ah, Al, Bch, Bcl, Vf, d_next, Pnh, Pnl, thr);
        }
    }
}

// round 14
// speedup vs baseline: 1.8020x; 1.0365x over previous
#include <cuda_runtime.h>
#include <cuda_fp16.h>
#include <cstdint>

#define B_ 8192
#define M_ 256
#define N_ 512
#define NITER_ 16

// ---------------- device scratch (no allocation allowed) --------------------
__device__ __align__(128) __half g_yh[(size_t)B_ * M_], g_yl[(size_t)B_ * M_];
__device__ __align__(128) __half g_Wh[N_ * M_], g_Wl[N_ * M_];
__device__ __align__(128) __half g_Dh[N_ * N_], g_Dl[N_ * N_];
__device__ __align__(128) __half g_Sth[N_ * N_], g_Stl[N_ * N_];
__device__ __align__(128) __half g_Eh[N_ * N_], g_El[N_ * N_];
// Concatenated B for the fused iteration kernel: rows 0..511 = D^T, rows 512..1023 = F = E@D^T
__device__ __align__(128) __half g_Bch[2 * N_ * N_], g_Bcl[2 * N_ * N_];
__device__ __align__(128) __half g_Wyh[(size_t)B_ * N_], g_Wyl[(size_t)B_ * N_];
// Ping-pong P buffers
__device__ __align__(128) __half g_Pah[(size_t)B_ * N_], g_Pal[(size_t)B_ * N_];
__device__ __align__(128) __half g_Pbh[(size_t)B_ * N_], g_Pbl[(size_t)B_ * N_];
__device__ __align__(128) float g_Vf[(size_t)B_ * N_];

// ---------------- PTX helpers (compute_103 baseline ISA only) ---------------
__device__ __forceinline__ uint32_t smem_u32(const void* p) {
    uint32_t a;
    asm("{ .reg .u64 t; cvta.to.shared.u64 t, %1; cvt.u32.u64 %0, t; }"
        : "=r"(a) : "l"(p));
    return a;
}

__device__ __forceinline__ void cp16(uint32_t saddr, const void* gaddr) {
    asm volatile("cp.async.cg.shared.global [%0], [%1], 16;"
                 :: "r"(saddr), "l"(gaddr));
}
__device__ __forceinline__ void cp_commit() {
    asm volatile("cp.async.commit_group;");
}
template <int N>
__device__ __forceinline__ void cp_wait() {
    asm volatile("cp.async.wait_group %0;" :: "n"(N));
}

__device__ __forceinline__ uint4 ldsm_x4(uint32_t addr) {
    uint4 r;
    asm volatile("ldmatrix.sync.aligned.m8n8.x4.shared.b16 {%0,%1,%2,%3}, [%4];"
                 : "=r"(r.x), "=r"(r.y), "=r"(r.z), "=r"(r.w) : "r"(addr));
    return r;
}

// fp16 x fp16 -> fp32 accumulate
__device__ __forceinline__ void mma16(float* c, uint4 a, uint32_t b0, uint32_t b1) {
    asm volatile(
        "mma.sync.aligned.m16n8k16.row.col.f32.f16.f16.f32 "
        "{%0,%1,%2,%3}, {%4,%5,%6,%7}, {%8,%9}, {%0,%1,%2,%3};"
        : "+f"(c[0]), "+f"(c[1]), "+f"(c[2]), "+f"(c[3])
        : "r"(a.x), "r"(a.y), "r"(a.z), "r"(a.w), "r"(b0), "r"(b1));
}

__device__ __forceinline__ float soft_thr_f(float u, float t) {
    return fmaxf(u - t, 0.f) - fmaxf(-u - t, 0.f);
}

__device__ __forceinline__ void split_h(float a, __half& h, __half& l) {
    h = __float2half(a);
    l = __float2half(a - __half2float(h));
}

// ---------------- prologue / elementwise kernels ----------------------------
__global__ void split_mat(const float* __restrict__ in,
                          __half* __restrict__ hi,
                          __half* __restrict__ lo, int n) {
    int i = (blockIdx.x * blockDim.x + threadIdx.x) * 4;
    if (i >= n) return;
    float4 v = *(const float4*)(in + i);
    float x[4] = {v.x, v.y, v.z, v.w};
    __half h[4], l[4];
    #pragma unroll
    for (int j = 0; j < 4; j++) split_h(x[j], h[j], l[j]);
    *(__half2*)(hi + i)     = __halves2half2(h[0], h[1]);
    *(__half2*)(hi + i + 2) = __halves2half2(h[2], h[3]);
    *(__half2*)(lo + i)     = __halves2half2(l[0], l[1]);
    *(__half2*)(lo + i + 2) = __halves2half2(l[2], l[3]);
}

// P0 = soft_thr(V) split  (d0 = 0 makes the first step trivial)
__global__ void thr_split(const float* __restrict__ V,
                          __half* __restrict__ hi,
                          __half* __restrict__ lo,
                          const float* __restrict__ thr, int n) {
    int i = (blockIdx.x * blockDim.x + threadIdx.x) * 4;
    if (i >= n) return;
    float theta = __ldg(thr);
    float4 v = *(const float4*)(V + i);
    float x[4] = {v.x, v.y, v.z, v.w};
    __half h[4], l[4];
    #pragma unroll
    for (int j = 0; j < 4; j++) split_h(soft_thr_f(x[j], theta), h[j], l[j]);
    *(__half2*)(hi + i)     = __halves2half2(h[0], h[1]);
    *(__half2*)(hi + i + 2) = __halves2half2(h[2], h[3]);
    *(__half2*)(lo + i)     = __halves2half2(l[0], l[1]);
    *(__half2*)(lo + i + 2) = __halves2half2(l[2], l[3]);
}

// out = in^T for 512x512, emitting fp16 hi/lo split
__global__ void transpose_split512(const float* __restrict__ in,
                                   __half* __restrict__ hi,
                                   __half* __restrict__ lo) {
    __shared__ float tile[32][33];
    int x = blockIdx.x * 32 + threadIdx.x;
    int y0 = blockIdx.y * 32;
    #pragma unroll
    for (int j = threadIdx.y; j < 32; j += 8)
        tile[j][threadIdx.x] = in[(size_t)(y0 + j) * N_ + x];
    __syncthreads();
    int xo = blockIdx.y * 32 + threadIdx.x;
    int yo0 = blockIdx.x * 32;
    #pragma unroll
    for (int j = threadIdx.y; j < 32; j += 8) {
        float v = tile[threadIdx.x][j];
        __half h, l;
        split_h(v, h, l);
        size_t o = (size_t)(yo0 + j) * N_ + xo;
        hi[o] = h;
        lo[o] = l;
    }
}

// ---------------- shared split-fp16 mainloop (mma.sync) ---------------------
// 128x128 CTA tile of A @ Bm^T.
// TERMS==3: ah*bh + al*bh + ah*bl — recurrence-grade.
// TERMS==2: ah*bh + al*bh (no BL loads) — output-grade.
// TERMS==1: ah*bh only (no AL/BL loads) — pure-output grade (~2.5e-4).
// SMEM per stage 64KB (AH/AL/BH/BL 16KB each), 3 stages, K-chunk 64, 1 CTA/SM.
// One __syncthreads per chunk: cp_wait -> sync -> issue(kt+2) -> mma.
static constexpr int OFF_AH = 0;
static constexpr int OFF_AL = 16384;
static constexpr int OFF_BH = 32768;
static constexpr int OFF_BL = 49152;
static constexpr int STG = 65536;
static constexpr int SMEM_TOTAL = 3 * STG;  // 196608

template <int TERMS>
__device__ __forceinline__ void issue_chunk(
    uint32_t stb, const __half* __restrict__ Ah, const __half* __restrict__ Al,
    const __half* __restrict__ Bh, const __half* __restrict__ Bl,
    int rowA0, int rowB0, int K, int kt, int tid) {
    #pragma unroll
    for (int i = 0; i < 4; i++) {
        int unit = tid + 256 * i;
        int row = unit >> 3, u = unit & 7;
        uint32_t so = (uint32_t)(row * 128 + ((u ^ (row & 7)) << 4));
        size_t goA = (size_t)(rowA0 + row) * K + kt * 64 + u * 8;
        size_t goB = (size_t)(rowB0 + row) * K + kt * 64 + u * 8;
        cp16(stb + OFF_AH + so, Ah + goA);
        if (TERMS >= 2) cp16(stb + OFF_AL + so, Al + goA);
        cp16(stb + OFF_BH + so, Bh + goB);
        if (TERMS == 3) cp16(stb + OFF_BL + so, Bl + goB);
    }
    cp_commit();
}

template <int TERMS>
__device__ __forceinline__ void mainloop_128x128(
    const __half* __restrict__ Ah, const __half* __restrict__ Al,
    const __half* __restrict__ Bh, const __half* __restrict__ Bl,
    int K, int rowA0, int rowB0, uint32_t sbase, int tid,
    float acc[4][4][4]) {
    const int lane = tid & 31;
    const int wid = tid >> 5;
    const int warp_m = wid & 1;
    const int warp_n = wid >> 1;

    const int rA = lane & 15;
    const int khA = lane >> 4;
    const int sxA = rA & 7;
    const int rB = ((lane >> 4) << 3) + (lane & 7);
    const int khB = (lane >> 3) & 1;
    const int sxB = rB & 7;

    uint32_t rowOffA[4], rowOffB[2];
    #pragma unroll
    for (int mi = 0; mi < 4; mi++)
        rowOffA[mi] = (warp_m * 64 + mi * 16 + rA) * 128;
    #pragma unroll
    for (int p = 0; p < 2; p++)
        rowOffB[p] = (warp_n * 32 + p * 16 + rB) * 128;

    const int KT = K >> 6;

    issue_chunk<TERMS>(sbase, Ah, Al, Bh, Bl, rowA0, rowB0, K, 0, tid);
    if (KT > 1) issue_chunk<TERMS>(sbase + STG, Ah, Al, Bh, Bl, rowA0, rowB0, K, 1, tid);

    int stage = 0;
    for (int kt = 0; kt < KT; kt++) {
        // Ensure chunk kt has landed (at most 1 newer group may stay pending).
        if (kt + 1 < KT) cp_wait<1>(); else cp_wait<0>();
        __syncthreads();
        // Safe to refill the stage all warps just vacated (kt-1's stage).
        if (kt + 2 < KT) {
            int s2 = stage + 2; if (s2 >= 3) s2 -= 3;
            issue_chunk<TERMS>(sbase + s2 * STG, Ah, Al, Bh, Bl, rowA0, rowB0, K, kt + 2, tid);
        }

        const uint32_t st = sbase + stage * STG;
        #pragma unroll
        for (int ks = 0; ks < 4; ks++) {
            const uint32_t uA = (uint32_t)(((ks * 2 + khA) ^ sxA) << 4);
            const uint32_t uB = (uint32_t)(((ks * 2 + khB) ^ sxB) << 4);

            uint4 bh0 = ldsm_x4(st + OFF_BH + rowOffB[0] + uB);
            uint4 bh1 = ldsm_x4(st + OFF_BH + rowOffB[1] + uB);
            uint4 bl0, bl1;
            if (TERMS == 3) {
                bl0 = ldsm_x4(st + OFF_BL + rowOffB[0] + uB);
                bl1 = ldsm_x4(st + OFF_BL + rowOffB[1] + uB);
            }

            #pragma unroll
            for (int mi = 0; mi < 4; mi++) {
                uint4 ah = ldsm_x4(st + OFF_AH + rowOffA[mi] + uA);
                mma16(acc[mi][0], ah, bh0.x, bh0.y);
                mma16(acc[mi][1], ah, bh0.z, bh0.w);
                mma16(acc[mi][2], ah, bh1.x, bh1.y);
                mma16(acc[mi][3], ah, bh1.z, bh1.w);
                if (TERMS >= 2) {
                    uint4 al = ldsm_x4(st + OFF_AL + rowOffA[mi] + uA);
                    mma16(acc[mi][0], al, bh0.x, bh0.y);
                    mma16(acc[mi][1], al, bh0.z, bh0.w);
                    mma16(acc[mi][2], al, bh1.x, bh1.y);
                    mma16(acc[mi][3], al, bh1.z, bh1.w);
                }
                if (TERMS == 3) {
                    mma16(acc[mi][0], ah, bl0.x, bl0.y);
                    mma16(acc[mi][1], ah, bl0.z, bl0.w);
                    mma16(acc[mi][2], ah, bl1.x, bl1.y);
                    mma16(acc[mi][3], ah, bl1.z, bl1.w);
                }
            }
        }
        if (++stage == 3) stage = 0;
    }
    // Final barrier so epilogue stores can't race a peer warp still reading smem
    __syncthreads();
}

#define INIT_ACC()                                                             \
    float acc[4][4][4];                                                        \
    _Pragma("unroll")                                                          \
    for (int a = 0; a < 4; a++)                                                \
        _Pragma("unroll")                                                      \
        for (int b = 0; b < 4; b++)                                            \
            _Pragma("unroll")                                                  \
            for (int c = 0; c < 4; c++) acc[a][b][c] = 0.f;

// ---------------- generic GEMM (prologue, 3-term) ---------------------------
template <bool WF32, bool WSPLIT>
__global__ __launch_bounds__(256, 1)
void gemm_tc(const __half* __restrict__ Ah, const __half* __restrict__ Al,
             const __half* __restrict__ Bh, const __half* __restrict__ Bl,
             float* __restrict__ Cf,
             __half* __restrict__ Chi, __half* __restrict__ Clo,
             int K) {
    extern __shared__ char sm[];
    const uint32_t sbase = smem_u32(sm);
    const int tid = threadIdx.x;
    const int lane = tid & 31;
    const int wid = tid >> 5;
    const int warp_m = wid & 1;
    const int warp_n = wid >> 1;

    INIT_ACC();
    mainloop_128x128<3>(Ah, Al, Bh, Bl, K, blockIdx.y * 128, blockIdx.x * 128,
                        sbase, tid, acc);

    const int g = lane >> 2, tm = lane & 3;
    #pragma unroll
    for (int mi = 0; mi < 4; mi++) {
        #pragma unroll
        for (int half = 0; half < 2; half++) {
            const int row = blockIdx.y * 128 + warp_m * 64 + mi * 16 + g + half * 8;
            #pragma unroll
            for (int ni = 0; ni < 4; ni++) {
                const int col = blockIdx.x * 128 + warp_n * 32 + ni * 8 + tm * 2;
                size_t off = (size_t)row * N_ + col;
                float c0 = acc[mi][ni][half * 2 + 0];
                float c1 = acc[mi][ni][half * 2 + 1];
                if (WF32) *(float2*)(Cf + off) = make_float2(c0, c1);
                if (WSPLIT) {
                    __half h0, l0, h1, l1;
                    split_h(c0, h0, l0);
                    split_h(c1, h1, l1);
                    *(__half2*)(Chi + off) = __halves2half2(h0, h1);
                    *(__half2*)(Clo + off) = __halves2half2(l0, l1);
                }
            }
        }
    }
}

// ---------------- fused iteration GEMM --------------------------------------
// Grid (8, 64): bx 0..3 -> d_{t+1} = P @ Dt^T (fp32 to out slot) [1-term]
//               bx 4..7 -> P_{t+1} = soft_thr(P @ F^T + V) (split) [3-term]
// B operand = concatenated [Dt | F] (1024 x 512).
__global__ __launch_bounds__(256, 1)
void gemm_fused(const __half* __restrict__ Ph, const __half* __restrict__ Pl,
                const __half* __restrict__ Bch, const __half* __restrict__ Bcl,
                const float* __restrict__ Vf, float* __restrict__ outSlot,
                __half* __restrict__ Pnh, __half* __restrict__ Pnl,
                const float* __restrict__ thr) {
    extern __shared__ char sm[];
    const uint32_t sbase = smem_u32(sm);
    const int tid = threadIdx.x;
    const int lane = tid & 31;
    const int wid = tid >> 5;
    const int warp_m = wid & 1;
    const int warp_n = wid >> 1;
    const int bx = blockIdx.x, by = blockIdx.y;
    const bool isP = bx >= 4;

    INIT_ACC();
    if (isP) {
        mainloop_128x128<3>(Ph, Pl, Bch, Bcl, N_, by * 128, bx * 128, sbase, tid, acc);
    } else {
        mainloop_128x128<1>(Ph, Pl, Bch, Bcl, N_, by * 128, bx * 128, sbase, tid, acc);
    }

    const int colbase = (bx & 3) * 128;
    const float theta = __ldg(thr);
    const int g = lane >> 2, tm = lane & 3;

    #pragma unroll
    for (int mi = 0; mi < 4; mi++) {
        #pragma unroll
        for (int half = 0; half < 2; half++) {
            const int row = by * 128 + warp_m * 64 + mi * 16 + g + half * 8;
            #pragma unroll
            for (int ni = 0; ni < 4; ni++) {
                const int col = colbase + warp_n * 32 + ni * 8 + tm * 2;
                size_t off = (size_t)row * N_ + col;
                float c0 = acc[mi][ni][half * 2 + 0];
                float c1 = acc[mi][ni][half * 2 + 1];
                if (!isP) {
                    *(float2*)(outSlot + off) = make_float2(c0, c1);
                } else {
                    float2 v = *(const float2*)(Vf + off);
                    c0 = soft_thr_f(c0 + v.x, theta);
                    c1 = soft_thr_f(c1 + v.y, theta);
                    __half h0, l0, h1, l1;
                    split_h(c0, h0, l0);
                    split_h(c1, h1, l1);
                    *(__half2*)(Pnh + off) = __halves2half2(h0, h1);
                    *(__half2*)(Pnl + off) = __halves2half2(l0, l1);
                }
            }
        }
    }
}

// ---------------- launch ----------------------------------------------------
extern "C" void kernel_launch(void* const* d_in, const int* in_sizes, int n_in,
                              void* d_out, int out_size) {
    const float* y   = (const float*)d_in[0];  // (B, M)
    const float* S   = (const float*)d_in[1];  // (N, N)
    const float* W   = (const float*)d_in[2];  // (N, M)
    const float* D   = (const float*)d_in[3];  // (N, N)
    const float* thr = (const float*)d_in[4];  // (1, 1)
    float* out = (float*)d_out;                // (NITER+1, B, N)

    __half *yh, *yl, *Wh, *Wl, *Dh, *Dl, *Sth, *Stl, *Eh, *El;
    __half *Bch, *Bcl, *Wyh, *Wyl, *Pah, *Pal, *Pbh, *Pbl;
    float* Vf;
    cudaGetSymbolAddress((void**)&yh, g_yh);   cudaGetSymbolAddress((void**)&yl, g_yl);
    cudaGetSymbolAddress((void**)&Wh, g_Wh);   cudaGetSymbolAddress((void**)&Wl, g_Wl);
    cudaGetSymbolAddress((void**)&Dh, g_Dh);   cudaGetSymbolAddress((void**)&Dl, g_Dl);
    cudaGetSymbolAddress((void**)&Sth, g_Sth); cudaGetSymbolAddress((void**)&Stl, g_Stl);
    cudaGetSymbolAddress((void**)&Eh, g_Eh);   cudaGetSymbolAddress((void**)&El, g_El);
    cudaGetSymbolAddress((void**)&Bch, g_Bch); cudaGetSymbolAddress((void**)&Bcl, g_Bcl);
    cudaGetSymbolAddress((void**)&Wyh, g_Wyh); cudaGetSymbolAddress((void**)&Wyl, g_Wyl);
    cudaGetSymbolAddress((void**)&Pah, g_Pah); cudaGetSymbolAddress((void**)&Pal, g_Pal);
    cudaGetSymbolAddress((void**)&Pbh, g_Pbh); cudaGetSymbolAddress((void**)&Pbl, g_Pbl);
    cudaGetSymbolAddress((void**)&Vf, g_Vf);

    cudaFuncSetAttribute((const void*)gemm_tc<false, true>,
                         cudaFuncAttributeMaxDynamicSharedMemorySize, SMEM_TOTAL);
    cudaFuncSetAttribute((const void*)gemm_tc<true, false>,
                         cudaFuncAttributeMaxDynamicSharedMemorySize, SMEM_TOTAL);
    cudaFuncSetAttribute((const void*)gemm_fused,
                         cudaFuncAttributeMaxDynamicSharedMemorySize, SMEM_TOTAL);

    const size_t BN = (size_t)B_ * N_;
    dim3 tb(32, 8), tg(16, 16);
    dim3 gBig(N_ / 128, B_ / 128);   // (4, 64)
    dim3 gSmall(N_ / 128, N_ / 128); // (4, 4)
    dim3 gFull(8, B_ / 128);         // (8, 64)

    // ---- prologue ----
    split_mat<<<(B_ * M_ / 4 + 255) / 256, 256>>>(y, yh, yl, B_ * M_);
    split_mat<<<(N_ * M_ / 4 + 255) / 256, 256>>>(W, Wh, Wl, N_ * M_);
    split_mat<<<(N_ * N_ / 4 + 255) / 256, 256>>>(D, Dh, Dl, N_ * N_);
    transpose_split512<<<tg, tb>>>(S, Sth, Stl);          // S^T split
    transpose_split512<<<tg, tb>>>(D, Bch, Bcl);          // D^T -> Bcat rows 0..511

    // Wy = y @ W^T (K=256) -> split
    gemm_tc<false, true><<<gBig, 256, SMEM_TOTAL>>>(
        yh, yl, Wh, Wl, nullptr, Wyh, Wyl, M_);
    // E = D @ S = D @ St^T -> split
    gemm_tc<false, true><<<gSmall, 256, SMEM_TOTAL>>>(
        Dh, Dl, Sth, Stl, nullptr, Eh, El, N_);
    // V = Wy @ D^T -> fp32
    gemm_tc<true, false><<<gBig, 256, SMEM_TOTAL>>>(
        Wyh, Wyl, Dh, Dl, Vf, nullptr, nullptr, N_);
    // F = E @ D^T -> split into Bcat rows 512..1023
    gemm_tc<false, true><<<gSmall, 256, SMEM_TOTAL>>>(
        Eh, El, Dh, Dl, nullptr, Bch + (size_t)N_ * N_, Bcl + (size_t)N_ * N_, N_);

    // d0 = 0 slot; P0 = soft_thr(V)
    cudaMemsetAsync(out, 0, BN * sizeof(float));
    thr_split<<<((int)BN / 4 + 255) / 256, 256>>>(Vf, Pah, Pal, thr, (int)BN);

    // Iterations: launch t reads P_t, writes out[t+1] (=P_t@Dt^T, 1-term) and
    // P_{t+1} = soft_thr(P_t@F^T + V) (3-term). Last launch: d-half only.
    for (int t = 0; t < NITER_; t++) {
        float* d_next = out + (size_t)(t + 1) * BN;
        const __half* Ah = (t & 1) ? Pbh : Pah;
        const __half* Al = (t & 1) ? Pbl : Pal;
        __half* Pnh = (t & 1) ? Pah : Pbh;
        __half* Pnl = (t & 1) ? Pal : Pbl;
        if (t + 1 < NITER_) {
            gemm_fused<<<gFull, 256, SMEM_TOTAL>>>(
                Ah, Al, Bch, Bcl, Vf, d_next, Pnh, Pnl, thr);
        } else {
            gemm_fused<<<gBig, 256, SMEM_TOTAL>>>(
                Ah, Al, Bch, Bcl, Vf, d_next, Pnh, Pnl, thr);
        }
    }
}

// round 15
// speedup vs baseline: 1.9249x; 1.0682x over previous
#include <cuda_runtime.h>
#include <cuda_fp16.h>
#include <cstdint>

#define B_ 8192
#define M_ 256
#define N_ 512
#define NITER_ 16

// ---------------- device scratch (no allocation allowed) --------------------
__device__ __align__(128) __half g_yh[(size_t)B_ * M_], g_yl[(size_t)B_ * M_];
__device__ __align__(128) __half g_Wth[M_ * N_], g_Wtl[M_ * N_];   // W^T [256x512]
__device__ __align__(128) __half g_Dh[N_ * N_], g_Dl[N_ * N_];
__device__ __align__(128) __half g_Sth[N_ * N_], g_Stl[N_ * N_];
__device__ __align__(128) __half g_Eh[N_ * N_], g_El[N_ * N_];
__device__ __align__(128) __half g_Gh[N_ * M_], g_Gl[N_ * M_];     // G = D@W [512x256]
// Concatenated B for fused kernel: rows 0..511 = F = E@D^T (heavy half, low bid),
//                                  rows 512..1023 = D^T (light half, high bid)
__device__ __align__(128) __half g_Bch[2 * N_ * N_], g_Bcl[2 * N_ * N_];
// Ping-pong P buffers
__device__ __align__(128) __half g_Pah[(size_t)B_ * N_], g_Pal[(size_t)B_ * N_];
__device__ __align__(128) __half g_Pbh[(size_t)B_ * N_], g_Pbl[(size_t)B_ * N_];
__device__ __align__(128) float g_Vf[(size_t)B_ * N_];

// ---------------- PTX helpers (compute_103 baseline ISA only) ---------------
__device__ __forceinline__ uint32_t smem_u32(const void* p) {
    uint32_t a;
    asm("{ .reg .u64 t; cvta.to.shared.u64 t, %1; cvt.u32.u64 %0, t; }"
        : "=r"(a) : "l"(p));
    return a;
}

__device__ __forceinline__ void cp16(uint32_t saddr, const void* gaddr) {
    asm volatile("cp.async.cg.shared.global [%0], [%1], 16;"
                 :: "r"(saddr), "l"(gaddr));
}
__device__ __forceinline__ void cp_commit() {
    asm volatile("cp.async.commit_group;");
}
template <int N>
__device__ __forceinline__ void cp_wait() {
    asm volatile("cp.async.wait_group %0;" :: "n"(N));
}

__device__ __forceinline__ uint4 ldsm_x4(uint32_t addr) {
    uint4 r;
    asm volatile("ldmatrix.sync.aligned.m8n8.x4.shared.b16 {%0,%1,%2,%3}, [%4];"
                 : "=r"(r.x), "=r"(r.y), "=r"(r.z), "=r"(r.w) : "r"(addr));
    return r;
}

// fp16 x fp16 -> fp32 accumulate
__device__ __forceinline__ void mma16(float* c, uint4 a, uint32_t b0, uint32_t b1) {
    asm volatile(
        "mma.sync.aligned.m16n8k16.row.col.f32.f16.f16.f32 "
        "{%0,%1,%2,%3}, {%4,%5,%6,%7}, {%8,%9}, {%0,%1,%2,%3};"
        : "+f"(c[0]), "+f"(c[1]), "+f"(c[2]), "+f"(c[3])
        : "r"(a.x), "r"(a.y), "r"(a.z), "r"(a.w), "r"(b0), "r"(b1));
}

__device__ __forceinline__ float soft_thr_f(float u, float t) {
    return fmaxf(u - t, 0.f) - fmaxf(-u - t, 0.f);
}

__device__ __forceinline__ void split_h(float a, __half& h, __half& l) {
    h = __float2half(a);
    l = __float2half(a - __half2float(h));
}

// ---------------- prologue / elementwise kernels ----------------------------
__global__ void split_mat(const float* __restrict__ in,
                          __half* __restrict__ hi,
                          __half* __restrict__ lo, int n) {
    int i = (blockIdx.x * blockDim.x + threadIdx.x) * 4;
    if (i >= n) return;
    float4 v = *(const float4*)(in + i);
    float x[4] = {v.x, v.y, v.z, v.w};
    __half h[4], l[4];
    #pragma unroll
    for (int j = 0; j < 4; j++) split_h(x[j], h[j], l[j]);
    *(__half2*)(hi + i)     = __halves2half2(h[0], h[1]);
    *(__half2*)(hi + i + 2) = __halves2half2(h[2], h[3]);
    *(__half2*)(lo + i)     = __halves2half2(l[0], l[1]);
    *(__half2*)(lo + i + 2) = __halves2half2(l[2], l[3]);
}

// P0 = soft_thr(V) split  (d0 = 0 makes the first step trivial)
__global__ void thr_split(const float* __restrict__ V,
                          __half* __restrict__ hi,
                          __half* __restrict__ lo,
                          const float* __restrict__ thr, int n) {
    int i = (blockIdx.x * blockDim.x + threadIdx.x) * 4;
    if (i >= n) return;
    float theta = __ldg(thr);
    float4 v = *(const float4*)(V + i);
    float x[4] = {v.x, v.y, v.z, v.w};
    __half h[4], l[4];
    #pragma unroll
    for (int j = 0; j < 4; j++) split_h(soft_thr_f(x[j], theta), h[j], l[j]);
    *(__half2*)(hi + i)     = __halves2half2(h[0], h[1]);
    *(__half2*)(hi + i + 2) = __halves2half2(h[2], h[3]);
    *(__half2*)(lo + i)     = __halves2half2(l[0], l[1]);
    *(__half2*)(lo + i + 2) = __halves2half2(l[2], l[3]);
}

// out[C x R] = in[R x C]^T, emitting fp16 hi/lo split. Grid (C/32, R/32), block (32,8).
__global__ void transpose_split(const float* __restrict__ in,
                                __half* __restrict__ hi,
                                __half* __restrict__ lo, int R, int C) {
    __shared__ float tile[32][33];
    int x = blockIdx.x * 32 + threadIdx.x;
    int y0 = blockIdx.y * 32;
    #pragma unroll
    for (int j = threadIdx.y; j < 32; j += 8)
        tile[j][threadIdx.x] = in[(size_t)(y0 + j) * C + x];
    __syncthreads();
    int xo = blockIdx.y * 32 + threadIdx.x;   // output col = input row
    int yo0 = blockIdx.x * 32;                // output row = input col
    #pragma unroll
    for (int j = threadIdx.y; j < 32; j += 8) {
        float v = tile[threadIdx.x][j];
        __half h, l;
        split_h(v, h, l);
        size_t o = (size_t)(yo0 + j) * R + xo;
        hi[o] = h;
        lo[o] = l;
    }
}

// ---------------- shared split-fp16 mainloop (mma.sync) ---------------------
// 128x128 CTA tile of A @ Bm^T.
// TERMS==3: ah*bh + al*bh + ah*bl — recurrence-grade.
// TERMS==1: ah*bh only (no AL/BL loads) — pure-output grade.
// SMEM per stage 64KB (AH/AL/BH/BL 16KB each), 3 stages, K-chunk 64, 1 CTA/SM.
static constexpr int OFF_AH = 0;
static constexpr int OFF_AL = 16384;
static constexpr int OFF_BH = 32768;
static constexpr int OFF_BL = 49152;
static constexpr int STG = 65536;
static constexpr int SMEM_TOTAL = 3 * STG;  // 196608

template <int TERMS>
__device__ __forceinline__ void issue_chunk(
    uint32_t stb, const __half* __restrict__ Ah, const __half* __restrict__ Al,
    const __half* __restrict__ Bh, const __half* __restrict__ Bl,
    int rowA0, int rowB0, int K, int kt, int tid) {
    #pragma unroll
    for (int i = 0; i < 4; i++) {
        int unit = tid + 256 * i;
        int row = unit >> 3, u = unit & 7;
        uint32_t so = (uint32_t)(row * 128 + ((u ^ (row & 7)) << 4));
        size_t goA = (size_t)(rowA0 + row) * K + kt * 64 + u * 8;
        size_t goB = (size_t)(rowB0 + row) * K + kt * 64 + u * 8;
        cp16(stb + OFF_AH + so, Ah + goA);
        if (TERMS >= 2) cp16(stb + OFF_AL + so, Al + goA);
        cp16(stb + OFF_BH + so, Bh + goB);
        if (TERMS == 3) cp16(stb + OFF_BL + so, Bl + goB);
    }
    cp_commit();
}

template <int TERMS>
__device__ __forceinline__ void mainloop_128x128(
    const __half* __restrict__ Ah, const __half* __restrict__ Al,
    const __half* __restrict__ Bh, const __half* __restrict__ Bl,
    int K, int rowA0, int rowB0, uint32_t sbase, int tid,
    float acc[4][4][4]) {
    const int lane = tid & 31;
    const int wid = tid >> 5;
    const int warp_m = wid & 1;
    const int warp_n = wid >> 1;

    const int rA = lane & 15;
    const int khA = lane >> 4;
    const int sxA = rA & 7;
    const int rB = ((lane >> 4) << 3) + (lane & 7);
    const int khB = (lane >> 3) & 1;
    const int sxB = rB & 7;

    uint32_t rowOffA[4], rowOffB[2];
    #pragma unroll
    for (int mi = 0; mi < 4; mi++)
        rowOffA[mi] = (warp_m * 64 + mi * 16 + rA) * 128;
    #pragma unroll
    for (int p = 0; p < 2; p++)
        rowOffB[p] = (warp_n * 32 + p * 16 + rB) * 128;

    const int KT = K >> 6;

    issue_chunk<TERMS>(sbase, Ah, Al, Bh, Bl, rowA0, rowB0, K, 0, tid);
    if (KT > 1) issue_chunk<TERMS>(sbase + STG, Ah, Al, Bh, Bl, rowA0, rowB0, K, 1, tid);

    int stage = 0;
    for (int kt = 0; kt < KT; kt++) {
        if (kt + 1 < KT) cp_wait<1>(); else cp_wait<0>();
        __syncthreads();
        if (kt + 2 < KT) {
            int s2 = stage + 2; if (s2 >= 3) s2 -= 3;
            issue_chunk<TERMS>(sbase + s2 * STG, Ah, Al, Bh, Bl, rowA0, rowB0, K, kt + 2, tid);
        }

        const uint32_t st = sbase + stage * STG;
        #pragma unroll
        for (int ks = 0; ks < 4; ks++) {
            const uint32_t uA = (uint32_t)(((ks * 2 + khA) ^ sxA) << 4);
            const uint32_t uB = (uint32_t)(((ks * 2 + khB) ^ sxB) << 4);

            uint4 bh0 = ldsm_x4(st + OFF_BH + rowOffB[0] + uB);
            uint4 bh1 = ldsm_x4(st + OFF_BH + rowOffB[1] + uB);
            uint4 bl0, bl1;
            if (TERMS == 3) {
                bl0 = ldsm_x4(st + OFF_BL + rowOffB[0] + uB);
                bl1 = ldsm_x4(st + OFF_BL + rowOffB[1] + uB);
            }

            #pragma unroll
            for (int mi = 0; mi < 4; mi++) {
                uint4 ah = ldsm_x4(st + OFF_AH + rowOffA[mi] + uA);
                mma16(acc[mi][0], ah, bh0.x, bh0.y);
                mma16(acc[mi][1], ah, bh0.z, bh0.w);
                mma16(acc[mi][2], ah, bh1.x, bh1.y);
                mma16(acc[mi][3], ah, bh1.z, bh1.w);
                if (TERMS >= 2) {
                    uint4 al = ldsm_x4(st + OFF_AL + rowOffA[mi] + uA);
                    mma16(acc[mi][0], al, bh0.x, bh0.y);
                    mma16(acc[mi][1], al, bh0.z, bh0.w);
                    mma16(acc[mi][2], al, bh1.x, bh1.y);
                    mma16(acc[mi][3], al, bh1.z, bh1.w);
                }
                if (TERMS == 3) {
                    mma16(acc[mi][0], ah, bl0.x, bl0.y);
                    mma16(acc[mi][1], ah, bl0.z, bl0.w);
                    mma16(acc[mi][2], ah, bl1.x, bl1.y);
                    mma16(acc[mi][3], ah, bl1.z, bl1.w);
                }
            }
        }
        if (++stage == 3) stage = 0;
    }
    __syncthreads();
}

#define INIT_ACC()                                                             \
    float acc[4][4][4];                                                        \
    _Pragma("unroll")                                                          \
    for (int a = 0; a < 4; a++)                                                \
        _Pragma("unroll")                                                      \
        for (int b = 0; b < 4; b++)                                            \
            _Pragma("unroll")                                                  \
            for (int c = 0; c < 4; c++) acc[a][b][c] = 0.f;

// ---------------- generic GEMM (prologue, 3-term) ---------------------------
template <bool WF32, bool WSPLIT>
__global__ __launch_bounds__(256, 1)
void gemm_tc(const __half* __restrict__ Ah, const __half* __restrict__ Al,
             const __half* __restrict__ Bh, const __half* __restrict__ Bl,
             float* __restrict__ Cf,
             __half* __restrict__ Chi, __half* __restrict__ Clo,
             int K, int Ncols) {
    extern __shared__ char sm[];
    const uint32_t sbase = smem_u32(sm);
    const int tid = threadIdx.x;
    const int lane = tid & 31;
    const int wid = tid >> 5;
    const int warp_m = wid & 1;
    const int warp_n = wid >> 1;

    INIT_ACC();
    mainloop_128x128<3>(Ah, Al, Bh, Bl, K, blockIdx.y * 128, blockIdx.x * 128,
                        sbase, tid, acc);

    const int g = lane >> 2, tm = lane & 3;
    #pragma unroll
    for (int mi = 0; mi < 4; mi++) {
        #pragma unroll
        for (int half = 0; half < 2; half++) {
            const int row = blockIdx.y * 128 + warp_m * 64 + mi * 16 + g + half * 8;
            #pragma unroll
            for (int ni = 0; ni < 4; ni++) {
                const int col = blockIdx.x * 128 + warp_n * 32 + ni * 8 + tm * 2;
                size_t off = (size_t)row * Ncols + col;
                float c0 = acc[mi][ni][half * 2 + 0];
                float c1 = acc[mi][ni][half * 2 + 1];
                if (WF32) *(float2*)(Cf + off) = make_float2(c0, c1);
                if (WSPLIT) {
                    __half h0, l0, h1, l1;
                    split_h(c0, h0, l0);
                    split_h(c1, h1, l1);
                    *(__half2*)(Chi + off) = __halves2half2(h0, h1);
                    *(__half2*)(Clo + off) = __halves2half2(l0, l1);
                }
            }
        }
    }
}

// ---------------- fused iteration GEMM (LPT: heavy P-tiles first) -----------
// bxEff = blockIdx.x + bxOff.
//   bxEff 0..3 -> P_{t+1} = soft_thr(P @ F^T + V) [3-term, HEAVY, low bid]
//   bxEff 4..7 -> d_{t+1} = P @ Dt^T -> out slot  [1-term, light, high bid]
// B operand = concatenated [F | Dt] (1024 x 512); rowB0 = bxEff*128.
__global__ __launch_bounds__(256, 1)
void gemm_fused(const __half* __restrict__ Ph, const __half* __restrict__ Pl,
                const __half* __restrict__ Bch, const __half* __restrict__ Bcl,
                const float* __restrict__ Vf, float* __restrict__ outSlot,
                __half* __restrict__ Pnh, __half* __restrict__ Pnl,
                const float* __restrict__ thr, int bxOff) {
    extern __shared__ char sm[];
    const uint32_t sbase = smem_u32(sm);
    const int tid = threadIdx.x;
    const int lane = tid & 31;
    const int wid = tid >> 5;
    const int warp_m = wid & 1;
    const int warp_n = wid >> 1;
    const int bxEff = blockIdx.x + bxOff;
    const int by = blockIdx.y;
    const bool isP = bxEff < 4;

    INIT_ACC();
    if (isP) {
        mainloop_128x128<3>(Ph, Pl, Bch, Bcl, N_, by * 128, bxEff * 128, sbase, tid, acc);
    } else {
        mainloop_128x128<1>(Ph, Pl, Bch, Bcl, N_, by * 128, bxEff * 128, sbase, tid, acc);
    }

    const int colbase = (bxEff & 3) * 128;
    const float theta = __ldg(thr);
    const int g = lane >> 2, tm = lane & 3;

    #pragma unroll
    for (int mi = 0; mi < 4; mi++) {
        #pragma unroll
        for (int half = 0; half < 2; half++) {
            const int row = by * 128 + warp_m * 64 + mi * 16 + g + half * 8;
            #pragma unroll
            for (int ni = 0; ni < 4; ni++) {
                const int col = colbase + warp_n * 32 + ni * 8 + tm * 2;
                size_t off = (size_t)row * N_ + col;
                float c0 = acc[mi][ni][half * 2 + 0];
                float c1 = acc[mi][ni][half * 2 + 1];
                if (!isP) {
                    *(float2*)(outSlot + off) = make_float2(c0, c1);
                } else {
                    float2 v = *(const float2*)(Vf + off);
                    c0 = soft_thr_f(c0 + v.x, theta);
                    c1 = soft_thr_f(c1 + v.y, theta);
                    __half h0, l0, h1, l1;
                    split_h(c0, h0, l0);
                    split_h(c1, h1, l1);
                    *(__half2*)(Pnh + off) = __halves2half2(h0, h1);
                    *(__half2*)(Pnl + off) = __halves2half2(l0, l1);
                }
            }
        }
    }
}

// ---------------- launch ----------------------------------------------------
extern "C" void kernel_launch(void* const* d_in, const int* in_sizes, int n_in,
                              void* d_out, int out_size) {
    const float* y   = (const float*)d_in[0];  // (B, M)
    const float* S   = (const float*)d_in[1];  // (N, N)
    const float* W   = (const float*)d_in[2];  // (N, M)
    const float* D   = (const float*)d_in[3];  // (N, N)
    const float* thr = (const float*)d_in[4];  // (1, 1)
    float* out = (float*)d_out;                // (NITER+1, B, N)

    __half *yh, *yl, *Wth, *Wtl, *Dh, *Dl, *Sth, *Stl, *Eh, *El, *Gh, *Gl;
    __half *Bch, *Bcl, *Pah, *Pal, *Pbh, *Pbl;
    float* Vf;
    cudaGetSymbolAddress((void**)&yh, g_yh);   cudaGetSymbolAddress((void**)&yl, g_yl);
    cudaGetSymbolAddress((void**)&Wth, g_Wth); cudaGetSymbolAddress((void**)&Wtl, g_Wtl);
    cudaGetSymbolAddress((void**)&Dh, g_Dh);   cudaGetSymbolAddress((void**)&Dl, g_Dl);
    cudaGetSymbolAddress((void**)&Sth, g_Sth); cudaGetSymbolAddress((void**)&Stl, g_Stl);
    cudaGetSymbolAddress((void**)&Eh, g_Eh);   cudaGetSymbolAddress((void**)&El, g_El);
    cudaGetSymbolAddress((void**)&Gh, g_Gh);   cudaGetSymbolAddress((void**)&Gl, g_Gl);
    cudaGetSymbolAddress((void**)&Bch, g_Bch); cudaGetSymbolAddress((void**)&Bcl, g_Bcl);
    cudaGetSymbolAddress((void**)&Pah, g_Pah); cudaGetSymbolAddress((void**)&Pal, g_Pal);
    cudaGetSymbolAddress((void**)&Pbh, g_Pbh); cudaGetSymbolAddress((void**)&Pbl, g_Pbl);
    cudaGetSymbolAddress((void**)&Vf, g_Vf);

    cudaFuncSetAttribute((const void*)gemm_tc<false, true>,
                         cudaFuncAttributeMaxDynamicSharedMemorySize, SMEM_TOTAL);
    cudaFuncSetAttribute((const void*)gemm_tc<true, false>,
                         cudaFuncAttributeMaxDynamicSharedMemorySize, SMEM_TOTAL);
    cudaFuncSetAttribute((const void*)gemm_fused,
                         cudaFuncAttributeMaxDynamicSharedMemorySize, SMEM_TOTAL);

    const size_t BN = (size_t)B_ * N_;
    dim3 tb(32, 8);
    dim3 tg512(16, 16);              // 512x512 transpose
    dim3 tgW(M_ / 32, N_ / 32);      // W [512x256] -> Wt [256x512]: (8, 16)
    dim3 gBig(N_ / 128, B_ / 128);   // (4, 64)
    dim3 gSmall(N_ / 128, N_ / 128); // (4, 4)
    dim3 gG(M_ / 128, N_ / 128);     // (2, 4)  G = D@W
    dim3 gFull(8, B_ / 128);         // (8, 64)
    dim3 gHalf(4, B_ / 128);         // (4, 64) final d-only

    // ---- prologue ----
    split_mat<<<(B_ * M_ / 4 + 255) / 256, 256>>>(y, yh, yl, B_ * M_);
    split_mat<<<(N_ * N_ / 4 + 255) / 256, 256>>>(D, Dh, Dl, N_ * N_);
    transpose_split<<<tg512, tb>>>(S, Sth, Stl, N_, N_);             // S^T
    transpose_split<<<tgW, tb>>>(W, Wth, Wtl, N_, M_);               // W^T [256x512]
    transpose_split<<<tg512, tb>>>(D, Bch + (size_t)N_ * N_,
                                   Bcl + (size_t)N_ * N_, N_, N_);   // D^T -> Bcat hi rows

    // E = D@S = D@(S^T)^T -> split
    gemm_tc<false, true><<<gSmall, 256, SMEM_TOTAL>>>(
        Dh, Dl, Sth, Stl, nullptr, Eh, El, N_, N_);
    // G = D@W = D@(W^T)^T -> split   [512 x 256]
    gemm_tc<false, true><<<gG, 256, SMEM_TOTAL>>>(
        Dh, Dl, Wth, Wtl, nullptr, Gh, Gl, N_, M_);
    // F = E@D^T -> split into Bcat rows 0..511 (heavy half, low bid)
    gemm_tc<false, true><<<gSmall, 256, SMEM_TOTAL>>>(
        Eh, El, Dh, Dl, nullptr, Bch, Bcl, N_, N_);
    // V = y@G^T (K = 256) -> fp32
    gemm_tc<true, false><<<gBig, 256, SMEM_TOTAL>>>(
        yh, yl, Gh, Gl, Vf, nullptr, nullptr, M_, N_);

    // d0 = 0 slot; P0 = soft_thr(V)
    cudaMemsetAsync(out, 0, BN * sizeof(float));
    thr_split<<<((int)BN / 4 + 255) / 256, 256>>>(Vf, Pah, Pal, thr, (int)BN);

    // Iterations: launch t reads P_t, writes out[t+1] (=P_t@Dt^T, 1-term, tail)
    // and P_{t+1} = soft_thr(P_t@F^T + V) (3-term, scheduled first).
    for (int t = 0; t < NITER_; t++) {
        float* d_next = out + (size_t)(t + 1) * BN;
        const __half* Ah = (t & 1) ? Pbh : Pah;
        const __half* Al = (t & 1) ? Pbl : Pal;
        __half* Pnh = (t & 1) ? Pah : Pbh;
        __half* Pnl = (t & 1) ? Pal : Pbl;
        if (t + 1 < NITER_) {
            gemm_fused<<<gFull, 256, SMEM_TOTAL>>>(
                Ah, Al, Bch, Bcl, Vf, d_next, Pnh, Pnl, thr, 0);
        } else {
            gemm_fused<<<gHalf, 256, SMEM_TOTAL>>>(
                Ah, Al, Bch, Bcl, Vf, d_next, Pnh, Pnl, thr, 4);
        }
    }
}

// round 16
// speedup vs baseline: 2.1839x; 1.1346x over previous
#include <cuda_runtime.h>
#include <cuda_fp16.h>
#include <cstdint>

#define B_ 8192
#define M_ 256
#define N_ 512
#define NITER_ 16

// ---------------- device scratch (no allocation allowed) --------------------
__device__ __align__(128) __half g_yh[(size_t)B_ * M_], g_yl[(size_t)B_ * M_];
__device__ __align__(128) __half g_Wth[M_ * N_], g_Wtl[M_ * N_];   // W^T [256x512]
__device__ __align__(128) __half g_Dh[N_ * N_], g_Dl[N_ * N_];
__device__ __align__(128) __half g_Sth[N_ * N_], g_Stl[N_ * N_];
__device__ __align__(128) __half g_Eh[N_ * N_], g_El[N_ * N_];
__device__ __align__(128) __half g_Gh[N_ * M_], g_Gl[N_ * M_];     // G = D@W [512x256]
// Concatenated B: rows 0..511 = F = E@D^T (heavy), rows 512..1023 = D^T (light)
__device__ __align__(128) __half g_Bch[2 * N_ * N_], g_Bcl[2 * N_ * N_];
// Ping-pong P buffers
__device__ __align__(128) __half g_Pah[(size_t)B_ * N_], g_Pal[(size_t)B_ * N_];
__device__ __align__(128) __half g_Pbh[(size_t)B_ * N_], g_Pbl[(size_t)B_ * N_];
__device__ __align__(128) float g_Vf[(size_t)B_ * N_];
// Dependency counters: cnt[t][by], stride 8 ints (32B) to spread lines. t=0..15.
__device__ __align__(128) int g_cnt[16 * 64 * 8];
__device__ __align__(128) int g_ticket[32];

// ---------------- PTX helpers (compute_103 baseline ISA only) ---------------
__device__ __forceinline__ uint32_t smem_u32(const void* p) {
    uint32_t a;
    asm("{ .reg .u64 t; cvta.to.shared.u64 t, %1; cvt.u32.u64 %0, t; }"
        : "=r"(a) : "l"(p));
    return a;
}

__device__ __forceinline__ void cp16(uint32_t saddr, const void* gaddr) {
    asm volatile("cp.async.cg.shared.global [%0], [%1], 16;"
                 :: "r"(saddr), "l"(gaddr));
}
__device__ __forceinline__ void cp_commit() {
    asm volatile("cp.async.commit_group;");
}
template <int N>
__device__ __forceinline__ void cp_wait() {
    asm volatile("cp.async.wait_group %0;" :: "n"(N));
}

__device__ __forceinline__ uint4 ldsm_x4(uint32_t addr) {
    uint4 r;
    asm volatile("ldmatrix.sync.aligned.m8n8.x4.shared.b16 {%0,%1,%2,%3}, [%4];"
                 : "=r"(r.x), "=r"(r.y), "=r"(r.z), "=r"(r.w) : "r"(addr));
    return r;
}

__device__ __forceinline__ void mma16(float* c, uint4 a, uint32_t b0, uint32_t b1) {
    asm volatile(
        "mma.sync.aligned.m16n8k16.row.col.f32.f16.f16.f32 "
        "{%0,%1,%2,%3}, {%4,%5,%6,%7}, {%8,%9}, {%0,%1,%2,%3};"
        : "+f"(c[0]), "+f"(c[1]), "+f"(c[2]), "+f"(c[3])
        : "r"(a.x), "r"(a.y), "r"(a.z), "r"(a.w), "r"(b0), "r"(b1));
}

__device__ __forceinline__ float soft_thr_f(float u, float t) {
    return fmaxf(u - t, 0.f) - fmaxf(-u - t, 0.f);
}

__device__ __forceinline__ void split_h(float a, __half& h, __half& l) {
    h = __float2half(a);
    l = __float2half(a - __half2float(h));
}

__device__ __forceinline__ void arrive_release(int* p) {
    asm volatile("red.release.gpu.global.add.s32 [%0], %1;" :: "l"(p), "r"(1) : "memory");
}

__device__ __forceinline__ void spin_acquire4(const int* p) {
    int v;
    while (true) {
        asm volatile("ld.acquire.gpu.global.s32 %0, [%1];" : "=r"(v) : "l"(p));
        if (v >= 4) return;
        __nanosleep(128);
    }
}

// ---------------- prologue / elementwise kernels ----------------------------
__global__ void split_mat(const float* __restrict__ in,
                          __half* __restrict__ hi,
                          __half* __restrict__ lo, int n) {
    int i = (blockIdx.x * blockDim.x + threadIdx.x) * 4;
    if (i >= n) return;
    float4 v = *(const float4*)(in + i);
    float x[4] = {v.x, v.y, v.z, v.w};
    __half h[4], l[4];
    #pragma unroll
    for (int j = 0; j < 4; j++) split_h(x[j], h[j], l[j]);
    *(__half2*)(hi + i)     = __halves2half2(h[0], h[1]);
    *(__half2*)(hi + i + 2) = __halves2half2(h[2], h[3]);
    *(__half2*)(lo + i)     = __halves2half2(l[0], l[1]);
    *(__half2*)(lo + i + 2) = __halves2half2(l[2], l[3]);
}

// out[C x R] = in[R x C]^T, fp16 hi/lo split. Grid (C/32, R/32), block (32,8).
__global__ void transpose_split(const float* __restrict__ in,
                                __half* __restrict__ hi,
                                __half* __restrict__ lo, int R, int C) {
    __shared__ float tile[32][33];
    int x = blockIdx.x * 32 + threadIdx.x;
    int y0 = blockIdx.y * 32;
    #pragma unroll
    for (int j = threadIdx.y; j < 32; j += 8)
        tile[j][threadIdx.x] = in[(size_t)(y0 + j) * C + x];
    __syncthreads();
    int xo = blockIdx.y * 32 + threadIdx.x;
    int yo0 = blockIdx.x * 32;
    #pragma unroll
    for (int j = threadIdx.y; j < 32; j += 8) {
        float v = tile[threadIdx.x][j];
        __half h, l;
        split_h(v, h, l);
        size_t o = (size_t)(yo0 + j) * R + xo;
        hi[o] = h;
        lo[o] = l;
    }
}

// ---------------- shared split-fp16 mainloop (mma.sync) ---------------------
static constexpr int OFF_AH = 0;
static constexpr int OFF_AL = 16384;
static constexpr int OFF_BH = 32768;
static constexpr int OFF_BL = 49152;
static constexpr int STG = 65536;
static constexpr int SMEM_TOTAL = 3 * STG;  // 196608

template <int TERMS>
__device__ __forceinline__ void issue_chunk(
    uint32_t stb, const __half* __restrict__ Ah, const __half* __restrict__ Al,
    const __half* __restrict__ Bh, const __half* __restrict__ Bl,
    int rowA0, int rowB0, int K, int kt, int tid) {
    #pragma unroll
    for (int i = 0; i < 4; i++) {
        int unit = tid + 256 * i;
        int row = unit >> 3, u = unit & 7;
        uint32_t so = (uint32_t)(row * 128 + ((u ^ (row & 7)) << 4));
        size_t goA = (size_t)(rowA0 + row) * K + kt * 64 + u * 8;
        size_t goB = (size_t)(rowB0 + row) * K + kt * 64 + u * 8;
        cp16(stb + OFF_AH + so, Ah + goA);
        if (TERMS >= 2) cp16(stb + OFF_AL + so, Al + goA);
        cp16(stb + OFF_BH + so, Bh + goB);
        if (TERMS == 3) cp16(stb + OFF_BL + so, Bl + goB);
    }
    cp_commit();
}

template <int TERMS>
__device__ __forceinline__ void mainloop_128x128(
    const __half* __restrict__ Ah, const __half* __restrict__ Al,
    const __half* __restrict__ Bh, const __half* __restrict__ Bl,
    int K, int rowA0, int rowB0, uint32_t sbase, int tid,
    float acc[4][4][4]) {
    const int lane = tid & 31;
    const int wid = tid >> 5;
    const int warp_m = wid & 1;
    const int warp_n = wid >> 1;

    const int rA = lane & 15;
    const int khA = lane >> 4;
    const int sxA = rA & 7;
    const int rB = ((lane >> 4) << 3) + (lane & 7);
    const int khB = (lane >> 3) & 1;
    const int sxB = rB & 7;

    uint32_t rowOffA[4], rowOffB[2];
    #pragma unroll
    for (int mi = 0; mi < 4; mi++)
        rowOffA[mi] = (warp_m * 64 + mi * 16 + rA) * 128;
    #pragma unroll
    for (int p = 0; p < 2; p++)
        rowOffB[p] = (warp_n * 32 + p * 16 + rB) * 128;

    const int KT = K >> 6;

    issue_chunk<TERMS>(sbase, Ah, Al, Bh, Bl, rowA0, rowB0, K, 0, tid);
    if (KT > 1) issue_chunk<TERMS>(sbase + STG, Ah, Al, Bh, Bl, rowA0, rowB0, K, 1, tid);

    int stage = 0;
    for (int kt = 0; kt < KT; kt++) {
        if (kt + 1 < KT) cp_wait<1>(); else cp_wait<0>();
        __syncthreads();
        if (kt + 2 < KT) {
            int s2 = stage + 2; if (s2 >= 3) s2 -= 3;
            issue_chunk<TERMS>(sbase + s2 * STG, Ah, Al, Bh, Bl, rowA0, rowB0, K, kt + 2, tid);
        }

        const uint32_t st = sbase + stage * STG;
        #pragma unroll
        for (int ks = 0; ks < 4; ks++) {
            const uint32_t uA = (uint32_t)(((ks * 2 + khA) ^ sxA) << 4);
            const uint32_t uB = (uint32_t)(((ks * 2 + khB) ^ sxB) << 4);

            uint4 bh0 = ldsm_x4(st + OFF_BH + rowOffB[0] + uB);
            uint4 bh1 = ldsm_x4(st + OFF_BH + rowOffB[1] + uB);
            uint4 bl0, bl1;
            if (TERMS == 3) {
                bl0 = ldsm_x4(st + OFF_BL + rowOffB[0] + uB);
                bl1 = ldsm_x4(st + OFF_BL + rowOffB[1] + uB);
            }

            #pragma unroll
            for (int mi = 0; mi < 4; mi++) {
                uint4 ah = ldsm_x4(st + OFF_AH + rowOffA[mi] + uA);
                mma16(acc[mi][0], ah, bh0.x, bh0.y);
                mma16(acc[mi][1], ah, bh0.z, bh0.w);
                mma16(acc[mi][2], ah, bh1.x, bh1.y);
                mma16(acc[mi][3], ah, bh1.z, bh1.w);
                if (TERMS >= 2) {
                    uint4 al = ldsm_x4(st + OFF_AL + rowOffA[mi] + uA);
                    mma16(acc[mi][0], al, bh0.x, bh0.y);
                    mma16(acc[mi][1], al, bh0.z, bh0.w);
                    mma16(acc[mi][2], al, bh1.x, bh1.y);
                    mma16(acc[mi][3], al, bh1.z, bh1.w);
                }
                if (TERMS == 3) {
                    mma16(acc[mi][0], ah, bl0.x, bl0.y);
                    mma16(acc[mi][1], ah, bl0.z, bl0.w);
                    mma16(acc[mi][2], ah, bl1.x, bl1.y);
                    mma16(acc[mi][3], ah, bl1.z, bl1.w);
                }
            }
        }
        if (++stage == 3) stage = 0;
    }
    __syncthreads();
}

#define INIT_ACC()                                                             \
    float acc[4][4][4];                                                        \
    _Pragma("unroll")                                                          \
    for (int a = 0; a < 4; a++)                                                \
        _Pragma("unroll")                                                      \
        for (int b = 0; b < 4; b++)                                            \
            _Pragma("unroll")                                                  \
            for (int c = 0; c < 4; c++) acc[a][b][c] = 0.f;

// ---------------- prologue GEMM 1: E = D@S  and  G = D@W --------------------
// grid (6, 4): bx 0..3 -> E tile (B = S^T rows bx*128, Ncols 512)
//              bx 4..5 -> G tile (B = W^T rows (bx-4)*128, Ncols 256)
__global__ __launch_bounds__(256, 1)
void gemm_pro1(const __half* __restrict__ Dh, const __half* __restrict__ Dl,
               const __half* __restrict__ Sth, const __half* __restrict__ Stl,
               const __half* __restrict__ Wth, const __half* __restrict__ Wtl,
               __half* __restrict__ Eh, __half* __restrict__ El,
               __half* __restrict__ Gh, __half* __restrict__ Gl) {
    extern __shared__ char sm[];
    const uint32_t sbase = smem_u32(sm);
    const int tid = threadIdx.x;
    const int lane = tid & 31;
    const int wid = tid >> 5;
    const int warp_m = wid & 1;
    const int warp_n = wid >> 1;
    const int bx = blockIdx.x, by = blockIdx.y;
    const bool isE = bx < 4;
    const int bxe = isE ? bx : bx - 4;

    const __half* Bh = isE ? Sth : Wth;
    const __half* Bl = isE ? Stl : Wtl;
    __half* Ch = isE ? Eh : Gh;
    __half* Cl = isE ? El : Gl;
    const int Ncols = isE ? N_ : M_;

    INIT_ACC();
    mainloop_128x128<3>(Dh, Dl, Bh, Bl, N_, by * 128, bxe * 128, sbase, tid, acc);

    const int g = lane >> 2, tm = lane & 3;
    #pragma unroll
    for (int mi = 0; mi < 4; mi++) {
        #pragma unroll
        for (int half = 0; half < 2; half++) {
            const int row = by * 128 + warp_m * 64 + mi * 16 + g + half * 8;
            #pragma unroll
            for (int ni = 0; ni < 4; ni++) {
                const int col = bxe * 128 + warp_n * 32 + ni * 8 + tm * 2;
                size_t off = (size_t)row * Ncols + col;
                __half h0, l0, h1, l1;
                split_h(acc[mi][ni][half * 2 + 0], h0, l0);
                split_h(acc[mi][ni][half * 2 + 1], h1, l1);
                *(__half2*)(Ch + off) = __halves2half2(h0, h1);
                *(__half2*)(Cl + off) = __halves2half2(l0, l1);
            }
        }
    }
}

// ---------------- prologue GEMM 2: F = E@D^T  and  V = y@G^T (+P0) ----------
// grid (8, 64): bx 0..3          -> V tile (A=y K=256), epilogue: Vf + P0 split + arrive cnt[0]
//               bx 4..7, by 0..3 -> F tile (A=E K=512) -> Bcat rows 0..511 split
//               else             -> early exit
__global__ __launch_bounds__(256, 1)
void gemm_pro2(const __half* __restrict__ yh, const __half* __restrict__ yl,
               const __half* __restrict__ Gh, const __half* __restrict__ Gl,
               const __half* __restrict__ Eh, const __half* __restrict__ El,
               const __half* __restrict__ Dh, const __half* __restrict__ Dl,
               float* __restrict__ Vf,
               __half* __restrict__ P0h, __half* __restrict__ P0l,
               __half* __restrict__ Bch, __half* __restrict__ Bcl,
               const float* __restrict__ thr, int* __restrict__ cnt) {
    const int bx = blockIdx.x, by = blockIdx.y;
    const bool isV = bx < 4;
    if (!isV && by >= 4) return;

    extern __shared__ char sm[];
    const uint32_t sbase = smem_u32(sm);
    const int tid = threadIdx.x;
    const int lane = tid & 31;
    const int wid = tid >> 5;
    const int warp_m = wid & 1;
    const int warp_n = wid >> 1;

    INIT_ACC();
    if (isV) {
        mainloop_128x128<3>(yh, yl, Gh, Gl, M_, by * 128, bx * 128, sbase, tid, acc);
    } else {
        mainloop_128x128<3>(Eh, El, Dh, Dl, N_, by * 128, (bx - 4) * 128, sbase, tid, acc);
    }

    const float theta = __ldg(thr);
    const int g = lane >> 2, tm = lane & 3;
    const int colbase = (bx & 3) * 128;

    #pragma unroll
    for (int mi = 0; mi < 4; mi++) {
        #pragma unroll
        for (int half = 0; half < 2; half++) {
            const int row = by * 128 + warp_m * 64 + mi * 16 + g + half * 8;
            #pragma unroll
            for (int ni = 0; ni < 4; ni++) {
                const int col = colbase + warp_n * 32 + ni * 8 + tm * 2;
                size_t off = (size_t)row * N_ + col;
                float c0 = acc[mi][ni][half * 2 + 0];
                float c1 = acc[mi][ni][half * 2 + 1];
                __half h0, l0, h1, l1;
                if (isV) {
                    *(float2*)(Vf + off) = make_float2(c0, c1);
                    c0 = soft_thr_f(c0, theta);
                    c1 = soft_thr_f(c1, theta);
                    split_h(c0, h0, l0);
                    split_h(c1, h1, l1);
                    *(__half2*)(P0h + off) = __halves2half2(h0, h1);
                    *(__half2*)(P0l + off) = __halves2half2(l0, l1);
                } else {
                    split_h(c0, h0, l0);
                    split_h(c1, h1, l1);
                    *(__half2*)(Bch + off) = __halves2half2(h0, h1);
                    *(__half2*)(Bcl + off) = __halves2half2(l0, l1);
                }
            }
        }
    }

    if (isV) {
        __syncthreads();
        if (tid == 0) arrive_release(cnt + by * 8);  // cnt[0][by]
    }
}

// ---------------- persistent iteration kernel -------------------------------
// Jobs (7936 total), consumed in order via global ticket:
//   j in [0, 7680): t = j>>9, r = j&511
//     r < 256 : P-job  (by=r>>2, bx=r&3): P_{t+1} = soft_thr(P_t @ F^T + V)  [3-term]
//     r >= 256: d-job  (by, bx of r-256): out[t+1] = P_t @ Dt^T              [1-term]
//   j in [7680, 7936): t=15 d-jobs.
// Dependency: job at step t waits cnt[t][by] == 4; P-jobs arrive cnt[t+1][by].
static constexpr int TOTAL_JOBS = 15 * 512 + 256;

__global__ __launch_bounds__(256, 1)
void gemm_persist(const __half* __restrict__ Bch, const __half* __restrict__ Bcl,
                  const float* __restrict__ Vf, float* __restrict__ out,
                  __half* __restrict__ Pah, __half* __restrict__ Pal,
                  __half* __restrict__ Pbh, __half* __restrict__ Pbl,
                  const float* __restrict__ thr,
                  int* __restrict__ cnt, int* __restrict__ ticket) {
    extern __shared__ char sm[];
    const uint32_t sbase = smem_u32(sm);
    __shared__ int sjob;
    const int tid = threadIdx.x;
    const int lane = tid & 31;
    const int wid = tid >> 5;
    const int warp_m = wid & 1;
    const int warp_n = wid >> 1;
    const float theta = __ldg(thr);
    const size_t BN = (size_t)B_ * N_;

    while (true) {
        if (tid == 0) sjob = atomicAdd(ticket, 1);
        __syncthreads();
        const int j = sjob;
        if (j >= TOTAL_JOBS) return;

        int t, by, bx;
        bool isP;
        if (j < 7680) {
            t = j >> 9;
            int r = j & 511;
            if (r < 256) { isP = true;  by = r >> 2; bx = r & 3; }
            else         { isP = false; int r2 = r - 256; by = r2 >> 2; bx = r2 & 3; }
        } else {
            t = 15; isP = false;
            int r2 = j - 7680; by = r2 >> 2; bx = r2 & 3;
        }

        // Wait until all 4 P-tiles of row `by` at step t are complete.
        if (tid == 0) spin_acquire4(cnt + (t * 64 + by) * 8);
        __syncthreads();

        const __half* Ah = (t & 1) ? Pbh : Pah;
        const __half* Al = (t & 1) ? Pbl : Pal;

        INIT_ACC();
        if (isP) {
            mainloop_128x128<3>(Ah, Al, Bch, Bcl, N_, by * 128, bx * 128, sbase, tid, acc);
        } else {
            mainloop_128x128<1>(Ah, Al, Bch, Bcl, N_, by * 128, (4 + bx) * 128, sbase, tid, acc);
        }

        const int g = lane >> 2, tm = lane & 3;
        const int colbase = bx * 128;

        if (isP) {
            __half* Pnh = ((t + 1) & 1) ? Pbh : Pah;
            __half* Pnl = ((t + 1) & 1) ? Pbl : Pal;
            #pragma unroll
            for (int mi = 0; mi < 4; mi++) {
                #pragma unroll
                for (int half = 0; half < 2; half++) {
                    const int row = by * 128 + warp_m * 64 + mi * 16 + g + half * 8;
                    #pragma unroll
                    for (int ni = 0; ni < 4; ni++) {
                        const int col = colbase + warp_n * 32 + ni * 8 + tm * 2;
                        size_t off = (size_t)row * N_ + col;
                        float2 v = *(const float2*)(Vf + off);
                        float c0 = soft_thr_f(acc[mi][ni][half * 2 + 0] + v.x, theta);
                        float c1 = soft_thr_f(acc[mi][ni][half * 2 + 1] + v.y, theta);
                        __half h0, l0, h1, l1;
                        split_h(c0, h0, l0);
                        split_h(c1, h1, l1);
                        *(__half2*)(Pnh + off) = __halves2half2(h0, h1);
                        *(__half2*)(Pnl + off) = __halves2half2(l0, l1);
                    }
                }
            }
            __syncthreads();
            if (tid == 0) arrive_release(cnt + ((t + 1) * 64 + by) * 8);
        } else {
            float* slab = out + (size_t)(t + 1) * BN;
            #pragma unroll
            for (int mi = 0; mi < 4; mi++) {
                #pragma unroll
                for (int half = 0; half < 2; half++) {
                    const int row = by * 128 + warp_m * 64 + mi * 16 + g + half * 8;
                    #pragma unroll
                    for (int ni = 0; ni < 4; ni++) {
                        const int col = colbase + warp_n * 32 + ni * 8 + tm * 2;
                        size_t off = (size_t)row * N_ + col;
                        *(float2*)(slab + off) =
                            make_float2(acc[mi][ni][half * 2 + 0], acc[mi][ni][half * 2 + 1]);
                    }
                }
            }
        }
    }
}

// ---------------- launch ----------------------------------------------------
extern "C" void kernel_launch(void* const* d_in, const int* in_sizes, int n_in,
                              void* d_out, int out_size) {
    const float* y   = (const float*)d_in[0];  // (B, M)
    const float* S   = (const float*)d_in[1];  // (N, N)
    const float* W   = (const float*)d_in[2];  // (N, M)
    const float* D   = (const float*)d_in[3];  // (N, N)
    const float* thr = (const float*)d_in[4];  // (1, 1)
    float* out = (float*)d_out;                // (NITER+1, B, N)

    __half *yh, *yl, *Wth, *Wtl, *Dh, *Dl, *Sth, *Stl, *Eh, *El, *Gh, *Gl;
    __half *Bch, *Bcl, *Pah, *Pal, *Pbh, *Pbl;
    float* Vf;
    int *cnt, *ticket;
    cudaGetSymbolAddress((void**)&yh, g_yh);   cudaGetSymbolAddress((void**)&yl, g_yl);
    cudaGetSymbolAddress((void**)&Wth, g_Wth); cudaGetSymbolAddress((void**)&Wtl, g_Wtl);
    cudaGetSymbolAddress((void**)&Dh, g_Dh);   cudaGetSymbolAddress((void**)&Dl, g_Dl);
    cudaGetSymbolAddress((void**)&Sth, g_Sth); cudaGetSymbolAddress((void**)&Stl, g_Stl);
    cudaGetSymbolAddress((void**)&Eh, g_Eh);   cudaGetSymbolAddress((void**)&El, g_El);
    cudaGetSymbolAddress((void**)&Gh, g_Gh);   cudaGetSymbolAddress((void**)&Gl, g_Gl);
    cudaGetSymbolAddress((void**)&Bch, g_Bch); cudaGetSymbolAddress((void**)&Bcl, g_Bcl);
    cudaGetSymbolAddress((void**)&Pah, g_Pah); cudaGetSymbolAddress((void**)&Pal, g_Pal);
    cudaGetSymbolAddress((void**)&Pbh, g_Pbh); cudaGetSymbolAddress((void**)&Pbl, g_Pbl);
    cudaGetSymbolAddress((void**)&Vf, g_Vf);
    cudaGetSymbolAddress((void**)&cnt, g_cnt);
    cudaGetSymbolAddress((void**)&ticket, g_ticket);

    cudaFuncSetAttribute((const void*)gemm_pro1,
                         cudaFuncAttributeMaxDynamicSharedMemorySize, SMEM_TOTAL);
    cudaFuncSetAttribute((const void*)gemm_pro2,
                         cudaFuncAttributeMaxDynamicSharedMemorySize, SMEM_TOTAL);
    cudaFuncSetAttribute((const void*)gemm_persist,
                         cudaFuncAttributeMaxDynamicSharedMemorySize, SMEM_TOTAL);

    const size_t BN = (size_t)B_ * N_;
    dim3 tb(32, 8);
    dim3 tg512(16, 16);
    dim3 tgW(M_ / 32, N_ / 32);

    // Reset sync state + d0 slab (graph-replay safe: every replay identical).
    cudaMemsetAsync(cnt, 0, 16 * 64 * 8 * sizeof(int));
    cudaMemsetAsync(ticket, 0, 32 * sizeof(int));
    cudaMemsetAsync(out, 0, BN * sizeof(float));

    // ---- prologue ----
    split_mat<<<(B_ * M_ / 4 + 255) / 256, 256>>>(y, yh, yl, B_ * M_);
    split_mat<<<(N_ * N_ / 4 + 255) / 256, 256>>>(D, Dh, Dl, N_ * N_);
    transpose_split<<<tg512, tb>>>(S, Sth, Stl, N_, N_);             // S^T
    transpose_split<<<tgW, tb>>>(W, Wth, Wtl, N_, M_);               // W^T
    transpose_split<<<tg512, tb>>>(D, Bch + (size_t)N_ * N_,
                                   Bcl + (size_t)N_ * N_, N_, N_);   // D^T -> Bcat rows 512..1023

    // E = D@S, G = D@W (one launch)
    gemm_pro1<<<dim3(6, 4), 256, SMEM_TOTAL>>>(Dh, Dl, Sth, Stl, Wth, Wtl,
                                               Eh, El, Gh, Gl);
    // F = E@D^T (Bcat rows 0..511) and V = y@G^T (+ P0 = soft_thr(V) + cnt[0] arrivals)
    gemm_pro2<<<dim3(8, 64), 256, SMEM_TOTAL>>>(yh, yl, Gh, Gl, Eh, El, Dh, Dl,
                                                Vf, Pah, Pal, Bch, Bcl, thr, cnt);

    // ---- all 16 iterations in one persistent launch ----
    gemm_persist<<<148, 256, SMEM_TOTAL>>>(Bch, Bcl, Vf, out,
                                           Pah, Pal, Pbh, Pbl, thr, cnt, ticket);
}

// round 17
// speedup vs baseline: 2.2928x; 1.0499x over previous
#include <cuda_runtime.h>
#include <cuda_fp16.h>
#include <cstdint>

#define B_ 8192
#define M_ 256
#define N_ 512
#define NITER_ 16
#define NTHREADS 512

// ---------------- device scratch (no allocation allowed) --------------------
__device__ __align__(128) __half g_yh[(size_t)B_ * M_], g_yl[(size_t)B_ * M_];
__device__ __align__(128) __half g_Wth[M_ * N_], g_Wtl[M_ * N_];   // W^T [256x512]
__device__ __align__(128) __half g_Dh[N_ * N_], g_Dl[N_ * N_];
__device__ __align__(128) __half g_Sth[N_ * N_], g_Stl[N_ * N_];
__device__ __align__(128) __half g_Eh[N_ * N_], g_El[N_ * N_];
__device__ __align__(128) __half g_Gh[N_ * M_], g_Gl[N_ * M_];     // G = D@W [512x256]
// Concatenated B: rows 0..511 = F = E@D^T (heavy), rows 512..1023 = D^T (light)
__device__ __align__(128) __half g_Bch[2 * N_ * N_], g_Bcl[2 * N_ * N_];
// Ping-pong P buffers
__device__ __align__(128) __half g_Pah[(size_t)B_ * N_], g_Pal[(size_t)B_ * N_];
__device__ __align__(128) __half g_Pbh[(size_t)B_ * N_], g_Pbl[(size_t)B_ * N_];
__device__ __align__(128) float g_Vf[(size_t)B_ * N_];
// Dependency counters: cnt[t][by], stride 8 ints. t=0..15.
__device__ __align__(128) int g_cnt[16 * 64 * 8];
__device__ __align__(128) int g_ticket[32];

// ---------------- PTX helpers (compute_103 baseline ISA only) ---------------
__device__ __forceinline__ uint32_t smem_u32(const void* p) {
    uint32_t a;
    asm("{ .reg .u64 t; cvta.to.shared.u64 t, %1; cvt.u32.u64 %0, t; }"
        : "=r"(a) : "l"(p));
    return a;
}

__device__ __forceinline__ void cp16(uint32_t saddr, const void* gaddr) {
    asm volatile("cp.async.cg.shared.global [%0], [%1], 16;"
                 :: "r"(saddr), "l"(gaddr));
}
__device__ __forceinline__ void cp_commit() {
    asm volatile("cp.async.commit_group;");
}
template <int N>
__device__ __forceinline__ void cp_wait() {
    asm volatile("cp.async.wait_group %0;" :: "n"(N));
}

__device__ __forceinline__ uint4 ldsm_x4(uint32_t addr) {
    uint4 r;
    asm volatile("ldmatrix.sync.aligned.m8n8.x4.shared.b16 {%0,%1,%2,%3}, [%4];"
                 : "=r"(r.x), "=r"(r.y), "=r"(r.z), "=r"(r.w) : "r"(addr));
    return r;
}

__device__ __forceinline__ void mma16(float* c, uint4 a, uint32_t b0, uint32_t b1) {
    asm volatile(
        "mma.sync.aligned.m16n8k16.row.col.f32.f16.f16.f32 "
        "{%0,%1,%2,%3}, {%4,%5,%6,%7}, {%8,%9}, {%0,%1,%2,%3};"
        : "+f"(c[0]), "+f"(c[1]), "+f"(c[2]), "+f"(c[3])
        : "r"(a.x), "r"(a.y), "r"(a.z), "r"(a.w), "r"(b0), "r"(b1));
}

__device__ __forceinline__ float soft_thr_f(float u, float t) {
    return fmaxf(u - t, 0.f) - fmaxf(-u - t, 0.f);
}

__device__ __forceinline__ void split_h(float a, __half& h, __half& l) {
    h = __float2half(a);
    l = __float2half(a - __half2float(h));
}

__device__ __forceinline__ void arrive_release(int* p) {
    asm volatile("red.release.gpu.global.add.s32 [%0], %1;" :: "l"(p), "r"(1) : "memory");
}

__device__ __forceinline__ void spin_acquire4(const int* p) {
    int v;
    while (true) {
        asm volatile("ld.acquire.gpu.global.s32 %0, [%1];" : "=r"(v) : "l"(p));
        if (v >= 4) return;
        __nanosleep(128);
    }
}

// ---------------- prologue / elementwise kernels ----------------------------
__global__ void split_mat(const float* __restrict__ in,
                          __half* __restrict__ hi,
                          __half* __restrict__ lo, int n) {
    int i = (blockIdx.x * blockDim.x + threadIdx.x) * 4;
    if (i >= n) return;
    float4 v = *(const float4*)(in + i);
    float x[4] = {v.x, v.y, v.z, v.w};
    __half h[4], l[4];
    #pragma unroll
    for (int j = 0; j < 4; j++) split_h(x[j], h[j], l[j]);
    *(__half2*)(hi + i)     = __halves2half2(h[0], h[1]);
    *(__half2*)(hi + i + 2) = __halves2half2(h[2], h[3]);
    *(__half2*)(lo + i)     = __halves2half2(l[0], l[1]);
    *(__half2*)(lo + i + 2) = __halves2half2(l[2], l[3]);
}

// out[C x R] = in[R x C]^T, fp16 hi/lo split. Grid (C/32, R/32), block (32,8).
__global__ void transpose_split(const float* __restrict__ in,
                                __half* __restrict__ hi,
                                __half* __restrict__ lo, int R, int C) {
    __shared__ float tile[32][33];
    int x = blockIdx.x * 32 + threadIdx.x;
    int y0 = blockIdx.y * 32;
    #pragma unroll
    for (int j = threadIdx.y; j < 32; j += 8)
        tile[j][threadIdx.x] = in[(size_t)(y0 + j) * C + x];
    __syncthreads();
    int xo = blockIdx.y * 32 + threadIdx.x;
    int yo0 = blockIdx.x * 32;
    #pragma unroll
    for (int j = threadIdx.y; j < 32; j += 8) {
        float v = tile[threadIdx.x][j];
        __half h, l;
        split_h(v, h, l);
        size_t o = (size_t)(yo0 + j) * R + xo;
        hi[o] = h;
        lo[o] = l;
    }
}

// ---------------- shared split-fp16 mainloop (mma.sync, 512 thr) ------------
// 128x128 CTA tile, 16 warps in 4x4 grid, warp tile 32x32.
static constexpr int OFF_AH = 0;
static constexpr int OFF_AL = 16384;
static constexpr int OFF_BH = 32768;
static constexpr int OFF_BL = 49152;
static constexpr int STG = 65536;
static constexpr int SMEM_TOTAL = 3 * STG;  // 196608

template <int TERMS>
__device__ __forceinline__ void issue_chunk(
    uint32_t stb, const __half* __restrict__ Ah, const __half* __restrict__ Al,
    const __half* __restrict__ Bh, const __half* __restrict__ Bl,
    int rowA0, int rowB0, int K, int kt, int tid) {
    #pragma unroll
    for (int i = 0; i < 2; i++) {
        int unit = tid + NTHREADS * i;
        int row = unit >> 3, u = unit & 7;
        uint32_t so = (uint32_t)(row * 128 + ((u ^ (row & 7)) << 4));
        size_t goA = (size_t)(rowA0 + row) * K + kt * 64 + u * 8;
        size_t goB = (size_t)(rowB0 + row) * K + kt * 64 + u * 8;
        cp16(stb + OFF_AH + so, Ah + goA);
        if (TERMS >= 2) cp16(stb + OFF_AL + so, Al + goA);
        cp16(stb + OFF_BH + so, Bh + goB);
        if (TERMS == 3) cp16(stb + OFF_BL + so, Bl + goB);
    }
    cp_commit();
}

template <int TERMS>
__device__ __forceinline__ void mainloop_128x128(
    const __half* __restrict__ Ah, const __half* __restrict__ Al,
    const __half* __restrict__ Bh, const __half* __restrict__ Bl,
    int K, int rowA0, int rowB0, uint32_t sbase, int tid,
    float acc[2][4][4]) {
    const int lane = tid & 31;
    const int wid = tid >> 5;
    const int warp_m = wid & 3;    // 0..3 (32-row band)
    const int warp_n = wid >> 2;   // 0..3 (32-col band)

    const int rA = lane & 15;
    const int khA = lane >> 4;
    const int sxA = rA & 7;
    const int rB = ((lane >> 4) << 3) + (lane & 7);
    const int khB = (lane >> 3) & 1;
    const int sxB = rB & 7;

    uint32_t rowOffA[2], rowOffB[2];
    #pragma unroll
    for (int mi = 0; mi < 2; mi++)
        rowOffA[mi] = (warp_m * 32 + mi * 16 + rA) * 128;
    #pragma unroll
    for (int p = 0; p < 2; p++)
        rowOffB[p] = (warp_n * 32 + p * 16 + rB) * 128;

    const int KT = K >> 6;

    issue_chunk<TERMS>(sbase, Ah, Al, Bh, Bl, rowA0, rowB0, K, 0, tid);
    if (KT > 1) issue_chunk<TERMS>(sbase + STG, Ah, Al, Bh, Bl, rowA0, rowB0, K, 1, tid);

    int stage = 0;
    for (int kt = 0; kt < KT; kt++) {
        if (kt + 1 < KT) cp_wait<1>(); else cp_wait<0>();
        __syncthreads();
        if (kt + 2 < KT) {
            int s2 = stage + 2; if (s2 >= 3) s2 -= 3;
            issue_chunk<TERMS>(sbase + s2 * STG, Ah, Al, Bh, Bl, rowA0, rowB0, K, kt + 2, tid);
        }

        const uint32_t st = sbase + stage * STG;
        #pragma unroll
        for (int ks = 0; ks < 4; ks++) {
            const uint32_t uA = (uint32_t)(((ks * 2 + khA) ^ sxA) << 4);
            const uint32_t uB = (uint32_t)(((ks * 2 + khB) ^ sxB) << 4);

            uint4 bh0 = ldsm_x4(st + OFF_BH + rowOffB[0] + uB);
            uint4 bh1 = ldsm_x4(st + OFF_BH + rowOffB[1] + uB);
            uint4 bl0, bl1;
            if (TERMS == 3) {
                bl0 = ldsm_x4(st + OFF_BL + rowOffB[0] + uB);
                bl1 = ldsm_x4(st + OFF_BL + rowOffB[1] + uB);
            }

            #pragma unroll
            for (int mi = 0; mi < 2; mi++) {
                uint4 ah = ldsm_x4(st + OFF_AH + rowOffA[mi] + uA);
                mma16(acc[mi][0], ah, bh0.x, bh0.y);
                mma16(acc[mi][1], ah, bh0.z, bh0.w);
                mma16(acc[mi][2], ah, bh1.x, bh1.y);
                mma16(acc[mi][3], ah, bh1.z, bh1.w);
                if (TERMS >= 2) {
                    uint4 al = ldsm_x4(st + OFF_AL + rowOffA[mi] + uA);
                    mma16(acc[mi][0], al, bh0.x, bh0.y);
                    mma16(acc[mi][1], al, bh0.z, bh0.w);
                    mma16(acc[mi][2], al, bh1.x, bh1.y);
                    mma16(acc[mi][3], al, bh1.z, bh1.w);
                }
                if (TERMS == 3) {
                    mma16(acc[mi][0], ah, bl0.x, bl0.y);
                    mma16(acc[mi][1], ah, bl0.z, bl0.w);
                    mma16(acc[mi][2], ah, bl1.x, bl1.y);
                    mma16(acc[mi][3], ah, bl1.z, bl1.w);
                }
            }
        }
        if (++stage == 3) stage = 0;
    }
    __syncthreads();
}

#define INIT_ACC()                                                             \
    float acc[2][4][4];                                                        \
    _Pragma("unroll")                                                          \
    for (int a = 0; a < 2; a++)                                                \
        _Pragma("unroll")                                                      \
        for (int b = 0; b < 4; b++)                                            \
            _Pragma("unroll")                                                  \
            for (int c = 0; c < 4; c++) acc[a][b][c] = 0.f;

// Epilogue row/col helpers (warp tile 32x32)
#define EPI_ROW(by_) ((by_) * 128 + warp_m * 32 + mi * 16 + g + half * 8)
#define EPI_COL(cb_) ((cb_) + warp_n * 32 + ni * 8 + tm * 2)

// ---------------- prologue GEMM 1: E = D@S  and  G = D@W --------------------
__global__ __launch_bounds__(NTHREADS, 1)
void gemm_pro1(const __half* __restrict__ Dh, const __half* __restrict__ Dl,
               const __half* __restrict__ Sth, const __half* __restrict__ Stl,
               const __half* __restrict__ Wth, const __half* __restrict__ Wtl,
               __half* __restrict__ Eh, __half* __restrict__ El,
               __half* __restrict__ Gh, __half* __restrict__ Gl) {
    extern __shared__ char sm[];
    const uint32_t sbase = smem_u32(sm);
    const int tid = threadIdx.x;
    const int lane = tid & 31;
    const int wid = tid >> 5;
    const int warp_m = wid & 3;
    const int warp_n = wid >> 2;
    const int bx = blockIdx.x, by = blockIdx.y;
    const bool isE = bx < 4;
    const int bxe = isE ? bx : bx - 4;

    const __half* Bh = isE ? Sth : Wth;
    const __half* Bl = isE ? Stl : Wtl;
    __half* Ch = isE ? Eh : Gh;
    __half* Cl = isE ? El : Gl;
    const int Ncols = isE ? N_ : M_;

    INIT_ACC();
    mainloop_128x128<3>(Dh, Dl, Bh, Bl, N_, by * 128, bxe * 128, sbase, tid, acc);

    const int g = lane >> 2, tm = lane & 3;
    #pragma unroll
    for (int mi = 0; mi < 2; mi++) {
        #pragma unroll
        for (int half = 0; half < 2; half++) {
            #pragma unroll
            for (int ni = 0; ni < 4; ni++) {
                const int row = EPI_ROW(by);
                const int col = EPI_COL(bxe * 128);
                size_t off = (size_t)row * Ncols + col;
                __half h0, l0, h1, l1;
                split_h(acc[mi][ni][half * 2 + 0], h0, l0);
                split_h(acc[mi][ni][half * 2 + 1], h1, l1);
                *(__half2*)(Ch + off) = __halves2half2(h0, h1);
                *(__half2*)(Cl + off) = __halves2half2(l0, l1);
            }
        }
    }
}

// ---------------- prologue GEMM 2: F = E@D^T  and  V = y@G^T (+P0) ----------
__global__ __launch_bounds__(NTHREADS, 1)
void gemm_pro2(const __half* __restrict__ yh, const __half* __restrict__ yl,
               const __half* __restrict__ Gh, const __half* __restrict__ Gl,
               const __half* __restrict__ Eh, const __half* __restrict__ El,
               const __half* __restrict__ Dh, const __half* __restrict__ Dl,
               float* __restrict__ Vf,
               __half* __restrict__ P0h, __half* __restrict__ P0l,
               __half* __restrict__ Bch, __half* __restrict__ Bcl,
               const float* __restrict__ thr, int* __restrict__ cnt) {
    const int bx = blockIdx.x, by = blockIdx.y;
    const bool isV = bx < 4;
    if (!isV && by >= 4) return;

    extern __shared__ char sm[];
    const uint32_t sbase = smem_u32(sm);
    const int tid = threadIdx.x;
    const int lane = tid & 31;
    const int wid = tid >> 5;
    const int warp_m = wid & 3;
    const int warp_n = wid >> 2;

    INIT_ACC();
    if (isV) {
        mainloop_128x128<3>(yh, yl, Gh, Gl, M_, by * 128, bx * 128, sbase, tid, acc);
    } else {
        mainloop_128x128<3>(Eh, El, Dh, Dl, N_, by * 128, (bx - 4) * 128, sbase, tid, acc);
    }

    const float theta = __ldg(thr);
    const int g = lane >> 2, tm = lane & 3;
    const int colbase = (bx & 3) * 128;

    #pragma unroll
    for (int mi = 0; mi < 2; mi++) {
        #pragma unroll
        for (int half = 0; half < 2; half++) {
            #pragma unroll
            for (int ni = 0; ni < 4; ni++) {
                const int row = EPI_ROW(by);
                const int col = EPI_COL(colbase);
                size_t off = (size_t)row * N_ + col;
                float c0 = acc[mi][ni][half * 2 + 0];
                float c1 = acc[mi][ni][half * 2 + 1];
                __half h0, l0, h1, l1;
                if (isV) {
                    *(float2*)(Vf + off) = make_float2(c0, c1);
                    c0 = soft_thr_f(c0, theta);
                    c1 = soft_thr_f(c1, theta);
                    split_h(c0, h0, l0);
                    split_h(c1, h1, l1);
                    *(__half2*)(P0h + off) = __halves2half2(h0, h1);
                    *(__half2*)(P0l + off) = __halves2half2(l0, l1);
                } else {
                    split_h(c0, h0, l0);
                    split_h(c1, h1, l1);
                    *(__half2*)(Bch + off) = __halves2half2(h0, h1);
                    *(__half2*)(Bcl + off) = __halves2half2(l0, l1);
                }
            }
        }
    }

    if (isV) {
        __syncthreads();
        if (tid == 0) arrive_release(cnt + by * 8);  // cnt[0][by]
    }
}

// ---------------- persistent iteration kernel -------------------------------
static constexpr int TOTAL_JOBS = 15 * 512 + 256;

__global__ __launch_bounds__(NTHREADS, 1)
void gemm_persist(const __half* __restrict__ Bch, const __half* __restrict__ Bcl,
                  const float* __restrict__ Vf, float* __restrict__ out,
                  __half* __restrict__ Pah, __half* __restrict__ Pal,
                  __half* __restrict__ Pbh, __half* __restrict__ Pbl,
                  const float* __restrict__ thr,
                  int* __restrict__ cnt, int* __restrict__ ticket) {
    extern __shared__ char sm[];
    const uint32_t sbase = smem_u32(sm);
    __shared__ int sjob;
    const int tid = threadIdx.x;
    const int lane = tid & 31;
    const int wid = tid >> 5;
    const int warp_m = wid & 3;
    const int warp_n = wid >> 2;
    const float theta = __ldg(thr);
    const size_t BN = (size_t)B_ * N_;

    while (true) {
        if (tid == 0) sjob = atomicAdd(ticket, 1);
        __syncthreads();
        const int j = sjob;
        if (j >= TOTAL_JOBS) return;

        int t, by, bx;
        bool isP;
        if (j < 7680) {
            t = j >> 9;
            int r = j & 511;
            if (r < 256) { isP = true;  by = r >> 2; bx = r & 3; }
            else         { isP = false; int r2 = r - 256; by = r2 >> 2; bx = r2 & 3; }
        } else {
            t = 15; isP = false;
            int r2 = j - 7680; by = r2 >> 2; bx = r2 & 3;
        }

        if (tid == 0) spin_acquire4(cnt + (t * 64 + by) * 8);
        __syncthreads();

        const __half* Ah = (t & 1) ? Pbh : Pah;
        const __half* Al = (t & 1) ? Pbl : Pal;

        INIT_ACC();
        if (isP) {
            mainloop_128x128<3>(Ah, Al, Bch, Bcl, N_, by * 128, bx * 128, sbase, tid, acc);
        } else {
            mainloop_128x128<1>(Ah, Al, Bch, Bcl, N_, by * 128, (4 + bx) * 128, sbase, tid, acc);
        }

        const int g = lane >> 2, tm = lane & 3;
        const int colbase = bx * 128;

        if (isP) {
            __half* Pnh = ((t + 1) & 1) ? Pbh : Pah;
            __half* Pnl = ((t + 1) & 1) ? Pbl : Pal;
            #pragma unroll
            for (int mi = 0; mi < 2; mi++) {
                #pragma unroll
                for (int half = 0; half < 2; half++) {
                    #pragma unroll
                    for (int ni = 0; ni < 4; ni++) {
                        const int row = EPI_ROW(by);
                        const int col = EPI_COL(colbase);
                        size_t off = (size_t)row * N_ + col;
                        float2 v = *(const float2*)(Vf + off);
                        float c0 = soft_thr_f(acc[mi][ni][half * 2 + 0] + v.x, theta);
                        float c1 = soft_thr_f(acc[mi][ni][half * 2 + 1] + v.y, theta);
                        __half h0, l0, h1, l1;
                        split_h(c0, h0, l0);
                        split_h(c1, h1, l1);
                        *(__half2*)(Pnh + off) = __halves2half2(h0, h1);
                        *(__half2*)(Pnl + off) = __halves2half2(l0, l1);
                    }
                }
            }
            __syncthreads();
            if (tid == 0) arrive_release(cnt + ((t + 1) * 64 + by) * 8);
        } else {
            float* slab = out + (size_t)(t + 1) * BN;
            #pragma unroll
            for (int mi = 0; mi < 2; mi++) {
                #pragma unroll
                for (int half = 0; half < 2; half++) {
                    #pragma unroll
                    for (int ni = 0; ni < 4; ni++) {
                        const int row = EPI_ROW(by);
                        const int col = EPI_COL(colbase);
                        size_t off = (size_t)row * N_ + col;
                        *(float2*)(slab + off) =
                            make_float2(acc[mi][ni][half * 2 + 0], acc[mi][ni][half * 2 + 1]);
                    }
                }
            }
        }
    }
}

// ---------------- launch ----------------------------------------------------
extern "C" void kernel_launch(void* const* d_in, const int* in_sizes, int n_in,
                              void* d_out, int out_size) {
    const float* y   = (const float*)d_in[0];  // (B, M)
    const float* S   = (const float*)d_in[1];  // (N, N)
    const float* W   = (const float*)d_in[2];  // (N, M)
    const float* D   = (const float*)d_in[3];  // (N, N)
    const float* thr = (const float*)d_in[4];  // (1, 1)
    float* out = (float*)d_out;                // (NITER+1, B, N)

    __half *yh, *yl, *Wth, *Wtl, *Dh, *Dl, *Sth, *Stl, *Eh, *El, *Gh, *Gl;
    __half *Bch, *Bcl, *Pah, *Pal, *Pbh, *Pbl;
    float* Vf;
    int *cnt, *ticket;
    cudaGetSymbolAddress((void**)&yh, g_yh);   cudaGetSymbolAddress((void**)&yl, g_yl);
    cudaGetSymbolAddress((void**)&Wth, g_Wth); cudaGetSymbolAddress((void**)&Wtl, g_Wtl);
    cudaGetSymbolAddress((void**)&Dh, g_Dh);   cudaGetSymbolAddress((void**)&Dl, g_Dl);
    cudaGetSymbolAddress((void**)&Sth, g_Sth); cudaGetSymbolAddress((void**)&Stl, g_Stl);
    cudaGetSymbolAddress((void**)&Eh, g_Eh);   cudaGetSymbolAddress((void**)&El, g_El);
    cudaGetSymbolAddress((void**)&Gh, g_Gh);   cudaGetSymbolAddress((void**)&Gl, g_Gl);
    cudaGetSymbolAddress((void**)&Bch, g_Bch); cudaGetSymbolAddress((void**)&Bcl, g_Bcl);
    cudaGetSymbolAddress((void**)&Pah, g_Pah); cudaGetSymbolAddress((void**)&Pal, g_Pal);
    cudaGetSymbolAddress((void**)&Pbh, g_Pbh); cudaGetSymbolAddress((void**)&Pbl, g_Pbl);
    cudaGetSymbolAddress((void**)&Vf, g_Vf);
    cudaGetSymbolAddress((void**)&cnt, g_cnt);
    cudaGetSymbolAddress((void**)&ticket, g_ticket);

    cudaFuncSetAttribute((const void*)gemm_pro1,
                         cudaFuncAttributeMaxDynamicSharedMemorySize, SMEM_TOTAL);
    cudaFuncSetAttribute((const void*)gemm_pro2,
                         cudaFuncAttributeMaxDynamicSharedMemorySize, SMEM_TOTAL);
    cudaFuncSetAttribute((const void*)gemm_persist,
                         cudaFuncAttributeMaxDynamicSharedMemorySize, SMEM_TOTAL);

    const size_t BN = (size_t)B_ * N_;
    dim3 tb(32, 8);
    dim3 tg512(16, 16);
    dim3 tgW(M_ / 32, N_ / 32);

    cudaMemsetAsync(cnt, 0, 16 * 64 * 8 * sizeof(int));
    cudaMemsetAsync(ticket, 0, 32 * sizeof(int));
    cudaMemsetAsync(out, 0, BN * sizeof(float));

    // ---- prologue ----
    split_mat<<<(B_ * M_ / 4 + 255) / 256, 256>>>(y, yh, yl, B_ * M_);
    split_mat<<<(N_ * N_ / 4 + 255) / 256, 256>>>(D, Dh, Dl, N_ * N_);
    transpose_split<<<tg512, tb>>>(S, Sth, Stl, N_, N_);
    transpose_split<<<tgW, tb>>>(W, Wth, Wtl, N_, M_);
    transpose_split<<<tg512, tb>>>(D, Bch + (size_t)N_ * N_,
                                   Bcl + (size_t)N_ * N_, N_, N_);

    gemm_pro1<<<dim3(6, 4), NTHREADS, SMEM_TOTAL>>>(Dh, Dl, Sth, Stl, Wth, Wtl,
                                                    Eh, El, Gh, Gl);
    gemm_pro2<<<dim3(8, 64), NTHREADS, SMEM_TOTAL>>>(yh, yl, Gh, Gl, Eh, El, Dh, Dl,
                                                     Vf, Pah, Pal, Bch, Bcl, thr, cnt);

    gemm_persist<<<148, NTHREADS, SMEM_TOTAL>>>(Bch, Bcl, Vf, out,
                                                Pah, Pal, Pbh, Pbl, thr, cnt, ticket);
}